// round 7
// baseline (speedup 1.0000x reference)
#include <cuda_runtime.h>
#include <cuda_bf16.h>
#include <mma.h>
#include <cstdint>
#include <math.h>

using namespace nvcuda;

// ---------------- problem constants ----------------
#define Bn   32
#define Sn   16
#define Ln   64
#define En   300
#define Pn   100
#define Hn   256
#define Gn   1024
#define DATT 612
#define N1   (Bn*Sn)
#define M1   (N1*Ln)
#define DIN1 (En+Pn)
#define NBATT 10            // ceil(612/64)

typedef unsigned long long u64;

// ---------------- scratch (device globals) ----------------------------------
__device__ float d_x[M1*DIN1];
__device__ float d_gpre[2*M1*Gn];
__device__ float d_z[M1*DATT];
__device__ float d_scp[M1*NBATT];
__device__ float d_scores[M1];
__device__ float d_senvec[N1*2*Hn];
__device__ float d_sx[N1*DATT];
__device__ float d_gpre2[2*N1*Gn];
__device__ float d_z2[N1*DATT];
__device__ float d_hT[2*Bn*Hn];
__device__ float d_scp2[N1*NBATT];
__device__ float d_scores2[N1];
__device__ float d_docvec[Bn*2*Hn];
__device__ float d_wWt[DATT*DATT];
__device__ float d_sWt[DATT*DATT];
__device__ float d_wtf[Hn*Gn];
__device__ float d_wtb[Hn*Gn];
__device__ float d_stf[Hn*Gn];
__device__ float d_stb[Hn*Gn];

__device__ __forceinline__ float sigmoidf(float x) { return 1.0f / (1.0f + expf(-x)); }

__device__ __forceinline__ void fma2(u64& d, u64 a, u64 b) {
    asm("fma.rn.f32x2 %0, %1, %2, %3;" : "=l"(d) : "l"(a), "l"(b), "l"(d));
}
__device__ __forceinline__ u64 pack2(float x, float y) {
    u64 r; asm("mov.b64 %0, {%1,%2};" : "=l"(r) : "f"(x), "f"(y)); return r;
}
__device__ __forceinline__ void unpack2(float& lo, float& hi, u64 v) {
    asm("mov.b64 {%0,%1}, %2;" : "=f"(lo), "=f"(hi) : "l"(v));
}

// ======================= WMMA split-bf16 GEMM ================================
// C[M,N] = A[M,K] @ W[N,K]^T (fp32 in/out), CTA tile 128x64, K-step 16.
// attn==0: C = acc + bias (row-major; M mult 128, N mult 64)
// attn!=0: C[m*gridDim.x + bx] = sum_n tanh(acc+bias[n])*proj[n]  (N edge ok)
// smem: bf16 tiles (12288B) | outs 128x64 f32 (32768B) | red 256 f32 (1024B)
#define GEMM_SMEM_BYTES (12288 + 32768 + 1024)

__global__ __launch_bounds__(256)
void gemm_wmma(const float* __restrict__ A, const float* __restrict__ W,
               const float* __restrict__ bias, const float* __restrict__ proj,
               float* __restrict__ C, int M, int N, int K, int attn)
{
    extern __shared__ float dynsm[];
    __nv_bfloat16* As_hi = (__nv_bfloat16*)dynsm;        // [128][16]
    __nv_bfloat16* As_lo = As_hi + 128*16;
    __nv_bfloat16* Bs_hi = As_lo + 128*16;               // [64][16]
    __nv_bfloat16* Bs_lo = Bs_hi + 64*16;
    float* outs = dynsm + 3072;                          // [128][64]
    float* red  = outs + 8192;                           // [256]

    const int tid = threadIdx.x;
    const int m0 = blockIdx.y * 128;
    const int n0 = blockIdx.x * 64;
    const int w  = tid >> 5;
    const int wm = w >> 1;          // 0..3
    const int wn = w & 1;           // 0..1

    wmma::fragment<wmma::accumulator, 16, 16, 16, float> acc[2][2];
#pragma unroll
    for (int i = 0; i < 2; i++)
#pragma unroll
        for (int j = 0; j < 2; j++)
            wmma::fill_fragment(acc[i][j], 0.0f);

    const int nk = (K + 15) / 16;
    const int arow  = tid >> 1;          // 0..127
    const int akoff = (tid & 1) * 8;
    const int brow  = tid & 63;          // 0..63
    const int bkoff = (tid >> 6) * 4;    // 0,4,8,12

    const float* __restrict__ pa = A + (size_t)(m0 + arow) * K;
    const bool bok = (n0 + brow) < N;
    const float* __restrict__ pb = W + (size_t)(n0 + brow) * K;

    for (int kc = 0; kc < nk; kc++) {
        const int kb = kc * 16;
#pragma unroll
        for (int j = 0; j < 8; j++) {
            int k = kb + akoff + j;
            float v = (k < K) ? pa[k] : 0.f;
            __nv_bfloat16 h = __float2bfloat16(v);
            __nv_bfloat16 l = __float2bfloat16(v - __bfloat162float(h));
            As_hi[arow*16 + akoff + j] = h;
            As_lo[arow*16 + akoff + j] = l;
        }
#pragma unroll
        for (int j = 0; j < 4; j++) {
            int k = kb + bkoff + j;
            float v = (bok && k < K) ? pb[k] : 0.f;
            __nv_bfloat16 h = __float2bfloat16(v);
            __nv_bfloat16 l = __float2bfloat16(v - __bfloat162float(h));
            Bs_hi[brow*16 + bkoff + j] = h;
            Bs_lo[brow*16 + bkoff + j] = l;
        }
        __syncthreads();

        wmma::fragment<wmma::matrix_a, 16, 16, 16, __nv_bfloat16, wmma::row_major> ah[2], al[2];
        wmma::fragment<wmma::matrix_b, 16, 16, 16, __nv_bfloat16, wmma::col_major> bh[2], bl[2];
#pragma unroll
        for (int i = 0; i < 2; i++) {
            wmma::load_matrix_sync(ah[i], As_hi + (wm*32 + i*16)*16, 16);
            wmma::load_matrix_sync(al[i], As_lo + (wm*32 + i*16)*16, 16);
            wmma::load_matrix_sync(bh[i], Bs_hi + (wn*32 + i*16)*16, 16);
            wmma::load_matrix_sync(bl[i], Bs_lo + (wn*32 + i*16)*16, 16);
        }
#pragma unroll
        for (int i = 0; i < 2; i++) {
#pragma unroll
            for (int j = 0; j < 2; j++) {
                wmma::mma_sync(acc[i][j], ah[i], bh[j], acc[i][j]);
                wmma::mma_sync(acc[i][j], ah[i], bl[j], acc[i][j]);
                wmma::mma_sync(acc[i][j], al[i], bh[j], acc[i][j]);
            }
        }
        __syncthreads();
    }

#pragma unroll
    for (int i = 0; i < 2; i++)
#pragma unroll
        for (int j = 0; j < 2; j++)
            wmma::store_matrix_sync(outs + (size_t)(wm*32 + i*16)*64 + wn*32 + j*16,
                                    acc[i][j], 64, wmma::mem_row_major);
    __syncthreads();

    if (attn == 0) {
        for (int i = tid; i < 128*64; i += 256) {
            int row = i >> 6;
            int col = i & 63;
            C[(size_t)(m0 + row) * N + n0 + col] = outs[i] + bias[n0 + col];
        }
    } else {
        const int row = tid >> 1;
        const int hf  = (tid & 1) * 32;
        float part = 0.f;
#pragma unroll
        for (int c = 0; c < 32; c++) {
            int n = n0 + hf + c;
            if (n < N) part += tanhf(outs[row*64 + hf + c] + bias[n]) * proj[n];
        }
        red[tid] = part;
        __syncthreads();
        if (tid < 128) {
            C[(size_t)(m0 + tid) * gridDim.x + blockIdx.x] = red[2*tid] + red[2*tid + 1];
        }
    }
}

// ---------------- gather ------------------------------------------------------
__global__ void gather_x_kernel(const int* __restrict__ tok,
                                const int* __restrict__ wpos,
                                const float* __restrict__ emb,
                                const float* __restrict__ wpe)
{
    int idx = blockIdx.x * blockDim.x + threadIdx.x;
    if (idx >= M1 * DIN1) return;
    int d = idx % DIN1;
    int m = idx / DIN1;
    float v;
    if (d < En) {
        v = emb[(size_t)tok[m] * En + d];
    } else {
        v = wpe[(size_t)wpos[m] * Pn + (d - En)];
        d_z[(size_t)m * DATT + 2*Hn + (d - En)] = v;
    }
    d_x[idx] = v;
}

// ---------------- transpose ----------------------------------------------------
__global__ void transpose_k(const float* __restrict__ W, float* __restrict__ Wt,
                            int Gr, int Kc)
{
    int idx = blockIdx.x * blockDim.x + threadIdx.x;
    if (idx >= Gr * Kc) return;
    int g = idx / Kc;
    int k = idx % Kc;
    Wt[(size_t)k * Gr + g] = W[idx];
}

// ---------------- word BiLSTM scan (8 rows/block) ------------------------------
__global__ __launch_bounds__(256, 1)
void lstm_scan_w(const float* __restrict__ gpre,
                 const float* __restrict__ Wt_f,
                 const float* __restrict__ Wt_b,
                 float* __restrict__ out,
                 int N, int T, int ostride)
{
    extern __shared__ float dynsm[];
    float* ws = dynsm;                 // [2][8][1024]
    float* hs = dynsm + 2*8*1024;      // [256][8]
    const int tid = threadIdx.x;
    const int nb  = N / 8;
    const int dir = blockIdx.x / nb;
    const int n0  = (blockIdx.x % nb) * 8;
    const float* __restrict__ Wt = dir ? Wt_b : Wt_f;

    float c[8];
#pragma unroll
    for (int r = 0; r < 8; r++) c[r] = 0.f;
    for (int i = tid; i < 256*8; i += 256) hs[i] = 0.f;

#pragma unroll
    for (int i = 0; i < 8; i++) {
        *(float4*)&ws[(tid + 256*i)*4] = *(const float4*)&Wt[(tid + 256*i)*4];
    }
    __syncthreads();

    const int NT = 32;
    for (int step = 0; step < T; step++) {
        const int tt = dir ? (T - 1 - step) : step;
        u64 acc2[4][4];
#pragma unroll
        for (int rp = 0; rp < 4; rp++) {
            size_t b0 = ((size_t)(dir*N + n0 + rp*2    ) * T + tt) * Gn;
            size_t b1 = ((size_t)(dir*N + n0 + rp*2 + 1) * T + tt) * Gn;
#pragma unroll
            for (int g = 0; g < 4; g++) {
                acc2[rp][g] = pack2(gpre[b0 + g*256 + tid], gpre[b1 + g*256 + tid]);
            }
        }
        for (int kt = 0; kt < NT; kt++) {
            const int cur = kt & 1;
            const bool last = (step == T-1) && (kt == NT-1);
            float4 pf[8];
            if (!last) {
                const float* src = &Wt[(size_t)((kt + 1) & 31) * 8192];
#pragma unroll
                for (int i = 0; i < 8; i++) {
                    pf[i] = *(const float4*)&src[(tid + 256*i)*4];
                }
            }
#pragma unroll
            for (int kk = 0; kk < 8; kk++) {
                const int k = kt*8 + kk;
                const float* wrow = &ws[(cur*8 + kk)*1024];
                float w0 = wrow[tid];
                float w1 = wrow[256+tid];
                float w2 = wrow[512+tid];
                float w3 = wrow[768+tid];
                u64 wd0 = pack2(w0,w0);
                u64 wd1 = pack2(w1,w1);
                u64 wd2 = pack2(w2,w2);
                u64 wd3 = pack2(w3,w3);
#pragma unroll
                for (int rp = 0; rp < 4; rp++) {
                    u64 h2 = *(const u64*)&hs[k*8 + rp*2];
                    fma2(acc2[rp][0], h2, wd0);
                    fma2(acc2[rp][1], h2, wd1);
                    fma2(acc2[rp][2], h2, wd2);
                    fma2(acc2[rp][3], h2, wd3);
                }
            }
            if (!last) {
                float* dst = &ws[(cur ^ 1) * 8192];
#pragma unroll
                for (int i = 0; i < 8; i++) {
                    *(float4*)&dst[(tid + 256*i)*4] = pf[i];
                }
            }
            __syncthreads();
        }
#pragma unroll
        for (int rp = 0; rp < 4; rp++) {
            float p0[2];
            float p1[2];
            float p2[2];
            float p3[2];
            unpack2(p0[0], p0[1], acc2[rp][0]);
            unpack2(p1[0], p1[1], acc2[rp][1]);
            unpack2(p2[0], p2[1], acc2[rp][2]);
            unpack2(p3[0], p3[1], acc2[rp][3]);
#pragma unroll
            for (int hh = 0; hh < 2; hh++) {
                int r = rp*2 + hh;
                float iv = sigmoidf(p0[hh]);
                float fv = sigmoidf(p1[hh]);
                float gv = tanhf(p2[hh]);
                float ov = sigmoidf(p3[hh]);
                c[r] = fv * c[r] + iv * gv;
                float hv = ov * tanhf(c[r]);
                hs[tid*8 + r] = hv;
                out[((size_t)(n0 + r) * T + tt) * ostride + dir*256 + tid] = hv;
            }
        }
        __syncthreads();
    }
}

// ---------------- sentence BiLSTM scan (1 row/block, keeps hT) ------------------
__global__ __launch_bounds__(256, 1)
void lstm_scan_s(const float* __restrict__ gpre,
                 const float* __restrict__ Wt_f,
                 const float* __restrict__ Wt_b,
                 float* __restrict__ out,
                 float* __restrict__ hT,
                 int N, int T, int ostride)
{
    extern __shared__ float dynsm[];
    float* ws = dynsm;
    float* hs = dynsm + 2*8*1024;
    const int tid = threadIdx.x;
    const int dir = blockIdx.x / N;
    const int n0  = blockIdx.x % N;
    const float* __restrict__ Wt = dir ? Wt_b : Wt_f;

    float c0 = 0.f;
    hs[tid] = 0.f;

#pragma unroll
    for (int i = 0; i < 8; i++) {
        *(float4*)&ws[(tid + 256*i)*4] = *(const float4*)&Wt[(tid + 256*i)*4];
    }
    __syncthreads();

    const int NT = 32;
    for (int step = 0; step < T; step++) {
        const int tt = dir ? (T - 1 - step) : step;
        float acc[4];
        size_t b0 = ((size_t)(dir*N + n0) * T + tt) * Gn;
#pragma unroll
        for (int g = 0; g < 4; g++) {
            acc[g] = gpre[b0 + g*256 + tid];
        }
        for (int kt = 0; kt < NT; kt++) {
            const int cur = kt & 1;
            const bool last = (step == T-1) && (kt == NT-1);
            float4 pf[8];
            if (!last) {
                const float* src = &Wt[(size_t)((kt + 1) & 31) * 8192];
#pragma unroll
                for (int i = 0; i < 8; i++) {
                    pf[i] = *(const float4*)&src[(tid + 256*i)*4];
                }
            }
#pragma unroll
            for (int kk = 0; kk < 8; kk++) {
                const int k = kt*8 + kk;
                const float* wrow = &ws[(cur*8 + kk)*1024];
                float hv = hs[k];
                acc[0] += hv * wrow[tid];
                acc[1] += hv * wrow[256+tid];
                acc[2] += hv * wrow[512+tid];
                acc[3] += hv * wrow[768+tid];
            }
            if (!last) {
                float* dst = &ws[(cur ^ 1) * 8192];
#pragma unroll
                for (int i = 0; i < 8; i++) {
                    *(float4*)&dst[(tid + 256*i)*4] = pf[i];
                }
            }
            __syncthreads();
        }
        float iv = sigmoidf(acc[0]);
        float fv = sigmoidf(acc[1]);
        float gv = tanhf(acc[2]);
        float ov = sigmoidf(acc[3]);
        c0 = fv * c0 + iv * gv;
        float hv = ov * tanhf(c0);
        hs[tid] = hv;
        out[((size_t)n0 * T + tt) * ostride + dir*256 + tid] = hv;
        if (step == T - 1) {
            hT[((size_t)dir * N + n0) * 256 + tid] = hv;
        }
        __syncthreads();
    }
}

// ---------------- attention glue -----------------------------------------------
__global__ void sum_scores(const float* __restrict__ scp, float* __restrict__ sc,
                           int M, int NB)
{
    int m = blockIdx.x * blockDim.x + threadIdx.x;
    if (m >= M) return;
    float s = 0.f;
    for (int j = 0; j < NB; j++) s += scp[(size_t)m * NB + j];
    sc[m] = s;
}

__global__ void softmax_pool_kernel(const float* __restrict__ sc,
                                    const float* __restrict__ hsrc,
                                    float* __restrict__ outv,
                                    int T, int stride)
{
    __shared__ float a[64];
    __shared__ float inv_s;
    int n = blockIdx.x;
    int tid = threadIdx.x;
    if (tid == 0) {
        float mx = -1e30f;
        for (int t = 0; t < T; t++) mx = fmaxf(mx, sc[n * T + t]);
        float sum = 0.f;
        for (int t = 0; t < T; t++) {
            float e = expf(sc[n * T + t] - mx);
            a[t] = e;
            sum += e;
        }
        inv_s = 1.f / sum;
    }
    __syncthreads();
    float inv = inv_s;
    for (int col = tid; col < 2*Hn; col += blockDim.x) {
        float acc = 0.f;
        for (int t = 0; t < T; t++) {
            acc += a[t] * hsrc[((size_t)n * T + t) * stride + col];
        }
        outv[(size_t)n * (2*Hn) + col] = acc * inv;
    }
}

__global__ void build_sx_kernel(const int* __restrict__ seg,
                                const float* __restrict__ spe)
{
    int idx = blockIdx.x * blockDim.x + threadIdx.x;
    if (idx >= N1 * DATT) return;
    int d = idx % DATT;
    int m = idx / DATT;
    d_sx[idx] = (d < 2*Hn) ? d_senvec[(size_t)m * (2*Hn) + d]
                           : spe[(size_t)seg[m] * Pn + (d - 2*Hn)];
}

__global__ void fill_z2pos(const int* __restrict__ seg, const float* __restrict__ spe)
{
    int idx = blockIdx.x * blockDim.x + threadIdx.x;
    if (idx >= N1 * Pn) return;
    int m = idx / Pn;
    int d = idx % Pn;
    d_z2[(size_t)m * DATT + 2*Hn + d] = spe[(size_t)seg[m] * Pn + d];
}

// ---------------- classifier head ------------------------------------------------
__global__ void final_dense_kernel(const float* __restrict__ dW,
                                   const float* __restrict__ db,
                                   float* __restrict__ outp)
{
    __shared__ float r0[128];
    __shared__ float r1[128];
    __shared__ float r2[128];
    int b = blockIdx.x;
    int tid = threadIdx.x;
    float a0 = 0.f, a1 = 0.f, a2 = 0.f;
    for (int k = tid; k < 4*Hn; k += 128) {
        float f;
        if (k < 2*Hn)      f = d_docvec[b * 2*Hn + k];
        else if (k < 3*Hn) f = d_hT[(0 * Bn + b) * Hn + (k - 2*Hn)];
        else               f = d_hT[(1 * Bn + b) * Hn + (k - 3*Hn)];
        a0 += f * dW[0*4*Hn + k];
        a1 += f * dW[1*4*Hn + k];
        a2 += f * dW[2*4*Hn + k];
    }
    r0[tid] = a0;
    r1[tid] = a1;
    r2[tid] = a2;
    __syncthreads();
    for (int s = 64; s > 0; s >>= 1) {
        if (tid < s) {
            r0[tid] += r0[tid+s];
            r1[tid] += r1[tid+s];
            r2[tid] += r2[tid+s];
        }
        __syncthreads();
    }
    if (tid == 0) {
        outp[b*3+0] = r0[0] + db[0];
        outp[b*3+1] = r1[0] + db[1];
        outp[b*3+2] = r2[0] + db[2];
    }
}

// ---------------- host driver ------------------------------------------------------
extern "C" void kernel_launch(void* const* d_in, const int* in_sizes, int n_in,
                              void* d_out, int out_size)
{
    const int*   tok     = (const int*)d_in[0];
    const int*   wpos    = (const int*)d_in[1];
    const int*   seg     = (const int*)d_in[2];
    const float* emb     = (const float*)d_in[3];
    const float* wpe     = (const float*)d_in[4];
    const float* spe     = (const float*)d_in[5];
    const float* wWih_f  = (const float*)d_in[6];
    const float* wWhh_f  = (const float*)d_in[7];
    const float* wb_f    = (const float*)d_in[8];
    const float* wWih_b  = (const float*)d_in[9];
    const float* wWhh_b  = (const float*)d_in[10];
    const float* wb_b    = (const float*)d_in[11];
    const float* sWih_f  = (const float*)d_in[12];
    const float* sWhh_f  = (const float*)d_in[13];
    const float* sb_f    = (const float*)d_in[14];
    const float* sWih_b  = (const float*)d_in[15];
    const float* sWhh_b  = (const float*)d_in[16];
    const float* sb_b    = (const float*)d_in[17];
    const float* word_W  = (const float*)d_in[18];
    const float* word_b  = (const float*)d_in[19];
    const float* word_p  = (const float*)d_in[20];
    const float* sent_W  = (const float*)d_in[21];
    const float* sent_b  = (const float*)d_in[22];
    const float* sent_p  = (const float*)d_in[23];
    const float* dense_W = (const float*)d_in[24];
    const float* dense_b = (const float*)d_in[25];
    float* outp = (float*)d_out;

    float *px, *pgpre, *pz, *pscp, *psc, *psenvec, *psx, *pgpre2, *pz2,
          *phT, *pscp2, *psc2, *pdocvec, *pwWt, *psWt, *pwtf, *pwtb, *pstf, *pstb;
    cudaGetSymbolAddress((void**)&px,      d_x);
    cudaGetSymbolAddress((void**)&pgpre,   d_gpre);
    cudaGetSymbolAddress((void**)&pz,      d_z);
    cudaGetSymbolAddress((void**)&pscp,    d_scp);
    cudaGetSymbolAddress((void**)&psc,     d_scores);
    cudaGetSymbolAddress((void**)&psenvec, d_senvec);
    cudaGetSymbolAddress((void**)&psx,     d_sx);
    cudaGetSymbolAddress((void**)&pgpre2,  d_gpre2);
    cudaGetSymbolAddress((void**)&pz2,     d_z2);
    cudaGetSymbolAddress((void**)&phT,     d_hT);
    cudaGetSymbolAddress((void**)&pscp2,   d_scp2);
    cudaGetSymbolAddress((void**)&psc2,    d_scores2);
    cudaGetSymbolAddress((void**)&pdocvec, d_docvec);
    cudaGetSymbolAddress((void**)&pwWt,    d_wWt);
    cudaGetSymbolAddress((void**)&psWt,    d_sWt);
    cudaGetSymbolAddress((void**)&pwtf,    d_wtf);
    cudaGetSymbolAddress((void**)&pwtb,    d_wtb);
    cudaGetSymbolAddress((void**)&pstf,    d_stf);
    cudaGetSymbolAddress((void**)&pstb,    d_stb);

    cudaFuncSetAttribute(lstm_scan_w, cudaFuncAttributeMaxDynamicSharedMemorySize,
                         2*8*1024*4 + 256*8*4);
    cudaFuncSetAttribute(lstm_scan_s, cudaFuncAttributeMaxDynamicSharedMemorySize,
                         2*8*1024*4 + 256*4);

    // 1. gather (also fills d_z pos columns)
    gather_x_kernel<<<(M1*DIN1 + 255)/256, 256>>>(tok, wpos, emb, wpe);

    // 2. weight transposes
    transpose_k<<<(Gn*Hn + 255)/256, 256>>>(wWhh_f, pwtf, Gn, Hn);
    transpose_k<<<(Gn*Hn + 255)/256, 256>>>(wWhh_b, pwtb, Gn, Hn);
    transpose_k<<<(Gn*Hn + 255)/256, 256>>>(sWhh_f, pstf, Gn, Hn);
    transpose_k<<<(Gn*Hn + 255)/256, 256>>>(sWhh_b, pstb, Gn, Hn);
    transpose_k<<<(DATT*DATT + 255)/256, 256>>>(word_W, pwWt, DATT, DATT);
    transpose_k<<<(DATT*DATT + 255)/256, 256>>>(sent_W, psWt, DATT, DATT);

    // 3. word input GEMMs (WMMA split-bf16)
    {
        dim3 g(Gn/64, M1/128);
        gemm_wmma<<<g, 256, GEMM_SMEM_BYTES>>>(px, wWih_f, wb_f, (const float*)0,
                                               pgpre, M1, Gn, DIN1, 0);
        gemm_wmma<<<g, 256, GEMM_SMEM_BYTES>>>(px, wWih_b, wb_b, (const float*)0,
                                               pgpre + (size_t)M1*Gn, M1, Gn, DIN1, 0);
    }

    // 4. word BiLSTM scan -> d_z cols [0,512)
    lstm_scan_w<<<128, 256, 2*8*1024*4 + 256*8*4>>>(pgpre, pwtf, pwtb, pz,
                                                    N1, Ln, DATT);

    // 5. word attention (fused tanh/proj epilogue)
    gemm_wmma<<<dim3(NBATT, M1/128), 256, GEMM_SMEM_BYTES>>>(pz, pwWt, word_b, word_p,
                                                             pscp, M1, DATT, DATT, 1);
    sum_scores<<<(M1 + 255)/256, 256>>>(pscp, psc, M1, NBATT);
    softmax_pool_kernel<<<N1, 256>>>(psc, pz, psenvec, Ln, DATT);

    // 6. sentence input
    build_sx_kernel<<<(N1*DATT + 255)/256, 256>>>(seg, spe);
    fill_z2pos<<<(N1*Pn + 255)/256, 256>>>(seg, spe);
    {
        dim3 g(Gn/64, N1/128);
        gemm_wmma<<<g, 256, GEMM_SMEM_BYTES>>>(psx, sWih_f, sb_f, (const float*)0,
                                               pgpre2, N1, Gn, DATT, 0);
        gemm_wmma<<<g, 256, GEMM_SMEM_BYTES>>>(psx, sWih_b, sb_b, (const float*)0,
                                               pgpre2 + (size_t)N1*Gn, N1, Gn, DATT, 0);
    }

    // 7. sentence BiLSTM scan -> d_z2 cols [0,512), keeps hT
    lstm_scan_s<<<2*Bn, 256, 2*8*1024*4 + 256*4>>>(pgpre2, pstf, pstb, pz2,
                                                   phT, Bn, Sn, DATT);

    // 8. sentence attention
    gemm_wmma<<<dim3(NBATT, N1/128), 256, GEMM_SMEM_BYTES>>>(pz2, psWt, sent_b, sent_p,
                                                             pscp2, N1, DATT, DATT, 1);
    sum_scores<<<(N1 + 255)/256, 256>>>(pscp2, psc2, N1, NBATT);
    softmax_pool_kernel<<<Bn, 256>>>(psc2, pz2, pdocvec, Sn, DATT);

    // 9. classifier head
    final_dense_kernel<<<Bn, 128>>>(dense_W, dense_b, outp);
}

// round 8
// speedup vs baseline: 1.2476x; 1.2476x over previous
#include <cuda_runtime.h>
#include <cuda_bf16.h>
#include <mma.h>
#include <cstdint>
#include <math.h>

using namespace nvcuda;

// ---------------- problem constants ----------------
#define Bn   32
#define Sn   16
#define Ln   64
#define En   300
#define Pn   100
#define Hn   256
#define Gn   1024
#define DATT 612
#define N1   (Bn*Sn)
#define M1   (N1*Ln)
#define DIN1 (En+Pn)
#define NBATT 10            // 640/64
#define XKP  416            // padded K for x (400)
#define ZKP  640            // padded K/N for 612

typedef unsigned long long u64;
typedef __nv_bfloat16 bf16;

// ---------------- scratch (device globals) ----------------------------------
__device__ float d_gpre[2*M1*Gn];
__device__ float d_z[M1*DATT];
__device__ float d_scp[M1*NBATT];
__device__ float d_scores[M1];
__device__ float d_senvec[N1*2*Hn];
__device__ float d_gpre2[2*N1*Gn];
__device__ float d_z2[N1*DATT];
__device__ float d_hT[2*Bn*Hn];
__device__ float d_scp2[N1*NBATT];
__device__ float d_scores2[N1];
__device__ float d_docvec[Bn*2*Hn];
__device__ float d_wtf[Hn*Gn];
__device__ float d_wtb[Hn*Gn];
__device__ float d_stf[Hn*Gn];
__device__ float d_stb[Hn*Gn];
// bf16 hi/lo GEMM operands (padded, zero-init padding persists)
__device__ bf16 g_xhi[M1*XKP];
__device__ bf16 g_xlo[M1*XKP];
__device__ bf16 g_zhi[(size_t)M1*ZKP];
__device__ bf16 g_zlo[(size_t)M1*ZKP];
__device__ bf16 g_sxhi[N1*ZKP];
__device__ bf16 g_sxlo[N1*ZKP];
__device__ bf16 g_z2hi[N1*ZKP];
__device__ bf16 g_z2lo[N1*ZKP];
__device__ bf16 g_wihf_hi[Gn*XKP];
__device__ bf16 g_wihf_lo[Gn*XKP];
__device__ bf16 g_wihb_hi[Gn*XKP];
__device__ bf16 g_wihb_lo[Gn*XKP];
__device__ bf16 g_sihf_hi[Gn*ZKP];
__device__ bf16 g_sihf_lo[Gn*ZKP];
__device__ bf16 g_sihb_hi[Gn*ZKP];
__device__ bf16 g_sihb_lo[Gn*ZKP];
__device__ bf16 g_wWt_hi[ZKP*ZKP];
__device__ bf16 g_wWt_lo[ZKP*ZKP];
__device__ bf16 g_sWt_hi[ZKP*ZKP];
__device__ bf16 g_sWt_lo[ZKP*ZKP];

__device__ __forceinline__ float sigmoidf(float x) { return 1.0f / (1.0f + expf(-x)); }

__device__ __forceinline__ void fma2(u64& d, u64 a, u64 b) {
    asm("fma.rn.f32x2 %0, %1, %2, %3;" : "=l"(d) : "l"(a), "l"(b), "l"(d));
}
__device__ __forceinline__ u64 pack2(float x, float y) {
    u64 r; asm("mov.b64 %0, {%1,%2};" : "=l"(r) : "f"(x), "f"(y)); return r;
}
__device__ __forceinline__ void unpack2(float& lo, float& hi, u64 v) {
    asm("mov.b64 {%0,%1}, %2;" : "=f"(lo), "=f"(hi) : "l"(v));
}
__device__ __forceinline__ void split_bf16(float v, bf16& h, bf16& l) {
    h = __float2bfloat16(v);
    l = __float2bfloat16(v - __bfloat162float(h));
}

// ======================= WMMA split-bf16 GEMM (bf16 inputs) ==================
// C[M,Nc] = A[M,KP] @ B[*,KP]^T, A/B pre-split bf16 hi/lo, KP mult of 32.
// attn==0: C[m*Nc + n] = acc + bias[n]
// attn!=0: C[m*gridDim.x + bx] = sum_{n<Nv} tanh(acc+bias[n])*proj[n]
#define GEMM_SMEM2 50176

__global__ __launch_bounds__(256)
void gemm_wb(const bf16* __restrict__ Ahi, const bf16* __restrict__ Alo,
             const bf16* __restrict__ Bhi, const bf16* __restrict__ Blo,
             const float* __restrict__ bias, const float* __restrict__ proj,
             float* __restrict__ C, int M, int Nc, int KP, int Nv, int attn)
{
    extern __shared__ float dynsm[];
    bf16* sb   = (bf16*)dynsm;       // tiles: 24576 bf16 = 49152 B
    float* outs = dynsm;             // reused after mainloop (32768 B)
    float* red  = dynsm + 12288;     // [256] at byte 49152

    const int tid = threadIdx.x;
    const int m0 = blockIdx.y * 128;
    const int n0 = blockIdx.x * 64;
    const int w  = tid >> 5;
    const int wm = w >> 1;           // 0..3
    const int wn = w & 1;            // 0..1

    wmma::fragment<wmma::accumulator, 16, 16, 16, float> acc[2][2];
#pragma unroll
    for (int i = 0; i < 2; i++)
#pragma unroll
        for (int j = 0; j < 2; j++)
            wmma::fill_fragment(acc[i][j], 0.0f);

    const int nk   = KP / 32;
    const int arow = tid >> 1;
    const int ak   = (tid & 1) * 16;
    const int brow = tid & 63;
    const int bk   = (tid >> 6) * 8;

    const bf16* __restrict__ pah = Ahi + (size_t)(m0 + arow) * KP + ak;
    const bf16* __restrict__ pal = Alo + (size_t)(m0 + arow) * KP + ak;
    const bf16* __restrict__ pbh = Bhi + (size_t)(n0 + brow) * KP + bk;
    const bf16* __restrict__ pbl = Blo + (size_t)(n0 + brow) * KP + bk;

    // preload chunk 0 straight into smem buffer 0
    {
        uint4 a0 = *(const uint4*)pah;
        uint4 a1 = *(const uint4*)(pah + 8);
        uint4 l0 = *(const uint4*)pal;
        uint4 l1 = *(const uint4*)(pal + 8);
        uint4 b0 = *(const uint4*)pbh;
        uint4 c0 = *(const uint4*)pbl;
        *(uint4*)(sb + arow*32 + ak)            = a0;
        *(uint4*)(sb + arow*32 + ak + 8)        = a1;
        *(uint4*)(sb + 8192 + arow*32 + ak)     = l0;
        *(uint4*)(sb + 8192 + arow*32 + ak + 8) = l1;
        *(uint4*)(sb + 16384 + brow*32 + bk)    = b0;
        *(uint4*)(sb + 20480 + brow*32 + bk)    = c0;
    }
    __syncthreads();

    for (int kc = 0; kc < nk; kc++) {
        const int cur = kc & 1;
        uint4 a0, a1, l0, l1, b0, c0;
        if (kc + 1 < nk) {
            const int off = (kc + 1) * 32;
            a0 = *(const uint4*)(pah + off);
            a1 = *(const uint4*)(pah + off + 8);
            l0 = *(const uint4*)(pal + off);
            l1 = *(const uint4*)(pal + off + 8);
            b0 = *(const uint4*)(pbh + off);
            c0 = *(const uint4*)(pbl + off);
        }
        const bf16* Ah = sb + cur*4096;
        const bf16* Al = sb + 8192 + cur*4096;
        const bf16* Bh = sb + 16384 + cur*2048;
        const bf16* Bl = sb + 20480 + cur*2048;
#pragma unroll
        for (int kf = 0; kf < 2; kf++) {
            wmma::fragment<wmma::matrix_a, 16, 16, 16, bf16, wmma::row_major> ah[2], al[2];
            wmma::fragment<wmma::matrix_b, 16, 16, 16, bf16, wmma::col_major> bh[2], bl[2];
#pragma unroll
            for (int i = 0; i < 2; i++) {
                wmma::load_matrix_sync(ah[i], Ah + (wm*32 + i*16)*32 + kf*16, 32);
                wmma::load_matrix_sync(al[i], Al + (wm*32 + i*16)*32 + kf*16, 32);
                wmma::load_matrix_sync(bh[i], Bh + (wn*32 + i*16)*32 + kf*16, 32);
                wmma::load_matrix_sync(bl[i], Bl + (wn*32 + i*16)*32 + kf*16, 32);
            }
#pragma unroll
            for (int i = 0; i < 2; i++) {
#pragma unroll
                for (int j = 0; j < 2; j++) {
                    wmma::mma_sync(acc[i][j], ah[i], bh[j], acc[i][j]);
                    wmma::mma_sync(acc[i][j], ah[i], bl[j], acc[i][j]);
                    wmma::mma_sync(acc[i][j], al[i], bh[j], acc[i][j]);
                }
            }
        }
        if (kc + 1 < nk) {
            const int nb = cur ^ 1;
            *(uint4*)(sb + nb*4096 + arow*32 + ak)            = a0;
            *(uint4*)(sb + nb*4096 + arow*32 + ak + 8)        = a1;
            *(uint4*)(sb + 8192 + nb*4096 + arow*32 + ak)     = l0;
            *(uint4*)(sb + 8192 + nb*4096 + arow*32 + ak + 8) = l1;
            *(uint4*)(sb + 16384 + nb*2048 + brow*32 + bk)    = b0;
            *(uint4*)(sb + 20480 + nb*2048 + brow*32 + bk)    = c0;
        }
        __syncthreads();
    }

    // epilogue: reuse smem as fp32 out tile [128][64]
#pragma unroll
    for (int i = 0; i < 2; i++)
#pragma unroll
        for (int j = 0; j < 2; j++)
            wmma::store_matrix_sync(outs + (size_t)(wm*32 + i*16)*64 + wn*32 + j*16,
                                    acc[i][j], 64, wmma::mem_row_major);
    __syncthreads();

    if (attn == 0) {
        for (int i = tid; i < 128*64; i += 256) {
            int row = i >> 6;
            int col = i & 63;
            C[(size_t)(m0 + row) * Nc + n0 + col] = outs[i] + bias[n0 + col];
        }
    } else {
        const int row = tid >> 1;
        const int hf  = (tid & 1) * 32;
        float part = 0.f;
#pragma unroll
        for (int c = 0; c < 32; c++) {
            int n = n0 + hf + c;
            if (n < Nv) part += tanhf(outs[row*64 + hf + c] + bias[n]) * proj[n];
        }
        red[tid] = part;
        __syncthreads();
        if (tid < 128) {
            C[(size_t)(m0 + tid) * gridDim.x + blockIdx.x] = red[2*tid] + red[2*tid + 1];
        }
    }
}

// ---------------- gather: x bf16 hi/lo + z pos cols bf16 ----------------------
__global__ void gather_x_kernel(const int* __restrict__ tok,
                                const int* __restrict__ wpos,
                                const float* __restrict__ emb,
                                const float* __restrict__ wpe)
{
    int idx = blockIdx.x * blockDim.x + threadIdx.x;
    if (idx >= M1 * DIN1) return;
    int d = idx % DIN1;
    int m = idx / DIN1;
    float v;
    if (d < En) {
        v = emb[(size_t)tok[m] * En + d];
    } else {
        v = wpe[(size_t)wpos[m] * Pn + (d - En)];
        bf16 h, l;
        split_bf16(v, h, l);
        size_t zi = (size_t)m * ZKP + 2*Hn + (d - En);
        g_zhi[zi] = h;
        g_zlo[zi] = l;
    }
    bf16 h, l;
    split_bf16(v, h, l);
    g_xhi[(size_t)m * XKP + d] = h;
    g_xlo[(size_t)m * XKP + d] = l;
}

__global__ void pad_x_kernel()
{
    int idx = blockIdx.x * blockDim.x + threadIdx.x;
    if (idx >= M1 * (XKP - DIN1)) return;
    int m = idx / (XKP - DIN1);
    int k = DIN1 + idx % (XKP - DIN1);
    g_xhi[(size_t)m * XKP + k] = __float2bfloat16(0.f);
    g_xlo[(size_t)m * XKP + k] = __float2bfloat16(0.f);
}

__global__ void pad_z_kernel()
{
    int idx = blockIdx.x * blockDim.x + threadIdx.x;
    if (idx >= M1 * (ZKP - DATT)) return;
    int m = idx / (ZKP - DATT);
    int k = DATT + idx % (ZKP - DATT);
    g_zhi[(size_t)m * ZKP + k] = __float2bfloat16(0.f);
    g_zlo[(size_t)m * ZKP + k] = __float2bfloat16(0.f);
}

// ---------------- weight conversions -------------------------------------------
// W[rows][kc] -> hi/lo[rows][kp], zero-padded
__global__ void conv_pad(const float* __restrict__ W, bf16* __restrict__ hi,
                         bf16* __restrict__ lo, int rows, int kc, int kp)
{
    int idx = blockIdx.x * blockDim.x + threadIdx.x;
    if (idx >= rows * kp) return;
    int r = idx / kp;
    int k = idx % kp;
    float v = (k < kc) ? W[(size_t)r * kc + k] : 0.f;
    bf16 h, l;
    split_bf16(v, h, l);
    hi[idx] = h;
    lo[idx] = l;
}

// W[d][d] -> transposed padded hi/lo[np][kp]: out[e][k] = W[k*d+e]
__global__ void conv_wt(const float* __restrict__ W, bf16* __restrict__ hi,
                        bf16* __restrict__ lo, int d, int np, int kp)
{
    int idx = blockIdx.x * blockDim.x + threadIdx.x;
    if (idx >= np * kp) return;
    int e = idx / kp;
    int k = idx % kp;
    float v = (e < d && k < d) ? W[(size_t)k * d + e] : 0.f;
    bf16 h, l;
    split_bf16(v, h, l);
    hi[idx] = h;
    lo[idx] = l;
}

// ---------------- transpose (Whh for scans) -------------------------------------
__global__ void transpose_k(const float* __restrict__ W, float* __restrict__ Wt,
                            int Gr, int Kc)
{
    int idx = blockIdx.x * blockDim.x + threadIdx.x;
    if (idx >= Gr * Kc) return;
    int g = idx / Kc;
    int k = idx % Kc;
    Wt[(size_t)k * Gr + g] = W[idx];
}

// ---------------- word BiLSTM scan (8 rows/block) ------------------------------
__global__ __launch_bounds__(256, 1)
void lstm_scan_w(const float* __restrict__ gpre,
                 const float* __restrict__ Wt_f,
                 const float* __restrict__ Wt_b,
                 float* __restrict__ out,
                 bf16* __restrict__ zhi, bf16* __restrict__ zlo,
                 int N, int T, int ostride)
{
    extern __shared__ float dynsm[];
    float* ws = dynsm;
    float* hs = dynsm + 2*8*1024;
    const int tid = threadIdx.x;
    const int nb  = N / 8;
    const int dir = blockIdx.x / nb;
    const int n0  = (blockIdx.x % nb) * 8;
    const float* __restrict__ Wt = dir ? Wt_b : Wt_f;

    float c[8];
#pragma unroll
    for (int r = 0; r < 8; r++) c[r] = 0.f;
    for (int i = tid; i < 256*8; i += 256) hs[i] = 0.f;

#pragma unroll
    for (int i = 0; i < 8; i++) {
        *(float4*)&ws[(tid + 256*i)*4] = *(const float4*)&Wt[(tid + 256*i)*4];
    }
    __syncthreads();

    const int NT = 32;
    for (int step = 0; step < T; step++) {
        const int tt = dir ? (T - 1 - step) : step;
        u64 acc2[4][4];
#pragma unroll
        for (int rp = 0; rp < 4; rp++) {
            size_t b0 = ((size_t)(dir*N + n0 + rp*2    ) * T + tt) * Gn;
            size_t b1 = ((size_t)(dir*N + n0 + rp*2 + 1) * T + tt) * Gn;
#pragma unroll
            for (int g = 0; g < 4; g++) {
                acc2[rp][g] = pack2(gpre[b0 + g*256 + tid], gpre[b1 + g*256 + tid]);
            }
        }
        for (int kt = 0; kt < NT; kt++) {
            const int cur = kt & 1;
            const bool last = (step == T-1) && (kt == NT-1);
            float4 pf[8];
            if (!last) {
                const float* src = &Wt[(size_t)((kt + 1) & 31) * 8192];
#pragma unroll
                for (int i = 0; i < 8; i++) {
                    pf[i] = *(const float4*)&src[(tid + 256*i)*4];
                }
            }
#pragma unroll
            for (int kk = 0; kk < 8; kk++) {
                const int k = kt*8 + kk;
                const float* wrow = &ws[(cur*8 + kk)*1024];
                float w0 = wrow[tid];
                float w1 = wrow[256+tid];
                float w2 = wrow[512+tid];
                float w3 = wrow[768+tid];
                u64 wd0 = pack2(w0,w0);
                u64 wd1 = pack2(w1,w1);
                u64 wd2 = pack2(w2,w2);
                u64 wd3 = pack2(w3,w3);
#pragma unroll
                for (int rp = 0; rp < 4; rp++) {
                    u64 h2 = *(const u64*)&hs[k*8 + rp*2];
                    fma2(acc2[rp][0], h2, wd0);
                    fma2(acc2[rp][1], h2, wd1);
                    fma2(acc2[rp][2], h2, wd2);
                    fma2(acc2[rp][3], h2, wd3);
                }
            }
            if (!last) {
                float* dst = &ws[(cur ^ 1) * 8192];
#pragma unroll
                for (int i = 0; i < 8; i++) {
                    *(float4*)&dst[(tid + 256*i)*4] = pf[i];
                }
            }
            __syncthreads();
        }
#pragma unroll
        for (int rp = 0; rp < 4; rp++) {
            float p0[2];
            float p1[2];
            float p2[2];
            float p3[2];
            unpack2(p0[0], p0[1], acc2[rp][0]);
            unpack2(p1[0], p1[1], acc2[rp][1]);
            unpack2(p2[0], p2[1], acc2[rp][2]);
            unpack2(p3[0], p3[1], acc2[rp][3]);
#pragma unroll
            for (int hh = 0; hh < 2; hh++) {
                int r = rp*2 + hh;
                float iv = sigmoidf(p0[hh]);
                float fv = sigmoidf(p1[hh]);
                float gv = tanhf(p2[hh]);
                float ov = sigmoidf(p3[hh]);
                c[r] = fv * c[r] + iv * gv;
                float hv = ov * tanhf(c[r]);
                hs[tid*8 + r] = hv;
                size_t mrow = (size_t)(n0 + r) * T + tt;
                out[mrow * ostride + dir*256 + tid] = hv;
                bf16 bh, bl;
                split_bf16(hv, bh, bl);
                zhi[mrow * ZKP + dir*256 + tid] = bh;
                zlo[mrow * ZKP + dir*256 + tid] = bl;
            }
        }
        __syncthreads();
    }
}

// ---------------- sentence BiLSTM scan (1 row/block, keeps hT) ------------------
__global__ __launch_bounds__(256, 1)
void lstm_scan_s(const float* __restrict__ gpre,
                 const float* __restrict__ Wt_f,
                 const float* __restrict__ Wt_b,
                 float* __restrict__ out,
                 bf16* __restrict__ zhi, bf16* __restrict__ zlo,
                 float* __restrict__ hT,
                 int N, int T, int ostride)
{
    extern __shared__ float dynsm[];
    float* ws = dynsm;
    float* hs = dynsm + 2*8*1024;
    const int tid = threadIdx.x;
    const int dir = blockIdx.x / N;
    const int n0  = blockIdx.x % N;
    const float* __restrict__ Wt = dir ? Wt_b : Wt_f;

    float c0 = 0.f;
    hs[tid] = 0.f;

#pragma unroll
    for (int i = 0; i < 8; i++) {
        *(float4*)&ws[(tid + 256*i)*4] = *(const float4*)&Wt[(tid + 256*i)*4];
    }
    __syncthreads();

    const int NT = 32;
    for (int step = 0; step < T; step++) {
        const int tt = dir ? (T - 1 - step) : step;
        float acc[4];
        size_t b0 = ((size_t)(dir*N + n0) * T + tt) * Gn;
#pragma unroll
        for (int g = 0; g < 4; g++) {
            acc[g] = gpre[b0 + g*256 + tid];
        }
        for (int kt = 0; kt < NT; kt++) {
            const int cur = kt & 1;
            const bool last = (step == T-1) && (kt == NT-1);
            float4 pf[8];
            if (!last) {
                const float* src = &Wt[(size_t)((kt + 1) & 31) * 8192];
#pragma unroll
                for (int i = 0; i < 8; i++) {
                    pf[i] = *(const float4*)&src[(tid + 256*i)*4];
                }
            }
#pragma unroll
            for (int kk = 0; kk < 8; kk++) {
                const int k = kt*8 + kk;
                const float* wrow = &ws[(cur*8 + kk)*1024];
                float hv = hs[k];
                acc[0] += hv * wrow[tid];
                acc[1] += hv * wrow[256+tid];
                acc[2] += hv * wrow[512+tid];
                acc[3] += hv * wrow[768+tid];
            }
            if (!last) {
                float* dst = &ws[(cur ^ 1) * 8192];
#pragma unroll
                for (int i = 0; i < 8; i++) {
                    *(float4*)&dst[(tid + 256*i)*4] = pf[i];
                }
            }
            __syncthreads();
        }
        float iv = sigmoidf(acc[0]);
        float fv = sigmoidf(acc[1]);
        float gv = tanhf(acc[2]);
        float ov = sigmoidf(acc[3]);
        c0 = fv * c0 + iv * gv;
        float hv = ov * tanhf(c0);
        hs[tid] = hv;
        size_t mrow = (size_t)n0 * T + tt;
        out[mrow * ostride + dir*256 + tid] = hv;
        bf16 bh, bl;
        split_bf16(hv, bh, bl);
        zhi[mrow * ZKP + dir*256 + tid] = bh;
        zlo[mrow * ZKP + dir*256 + tid] = bl;
        if (step == T - 1) {
            hT[((size_t)dir * N + n0) * 256 + tid] = hv;
        }
        __syncthreads();
    }
}

// ---------------- attention glue -----------------------------------------------
__global__ void sum_scores(const float* __restrict__ scp, float* __restrict__ sc,
                           int M, int NB)
{
    int m = blockIdx.x * blockDim.x + threadIdx.x;
    if (m >= M) return;
    float s = 0.f;
    for (int j = 0; j < NB; j++) s += scp[(size_t)m * NB + j];
    sc[m] = s;
}

__global__ void softmax_pool_kernel(const float* __restrict__ sc,
                                    const float* __restrict__ hsrc,
                                    float* __restrict__ outv,
                                    int T, int stride)
{
    __shared__ float a[64];
    __shared__ float inv_s;
    int n = blockIdx.x;
    int tid = threadIdx.x;
    if (tid == 0) {
        float mx = -1e30f;
        for (int t = 0; t < T; t++) mx = fmaxf(mx, sc[n * T + t]);
        float sum = 0.f;
        for (int t = 0; t < T; t++) {
            float e = expf(sc[n * T + t] - mx);
            a[t] = e;
            sum += e;
        }
        inv_s = 1.f / sum;
    }
    __syncthreads();
    float inv = inv_s;
    for (int col = tid; col < 2*Hn; col += blockDim.x) {
        float acc = 0.f;
        for (int t = 0; t < T; t++) {
            acc += a[t] * hsrc[((size_t)n * T + t) * stride + col];
        }
        outv[(size_t)n * (2*Hn) + col] = acc * inv;
    }
}

// sx bf16 build: [senvec | spe | 0-pad]
__global__ void build_sx_kernel(const int* __restrict__ seg,
                                const float* __restrict__ spe)
{
    int idx = blockIdx.x * blockDim.x + threadIdx.x;
    if (idx >= N1 * ZKP) return;
    int d = idx % ZKP;
    int m = idx / ZKP;
    float v;
    if (d < 2*Hn)      v = d_senvec[(size_t)m * (2*Hn) + d];
    else if (d < DATT) v = spe[(size_t)seg[m] * Pn + (d - 2*Hn)];
    else               v = 0.f;
    bf16 h, l;
    split_bf16(v, h, l);
    g_sxhi[idx] = h;
    g_sxlo[idx] = l;
}

// z2 pos cols + padding bf16
__global__ void fill_z2pos(const int* __restrict__ seg, const float* __restrict__ spe)
{
    int idx = blockIdx.x * blockDim.x + threadIdx.x;
    if (idx >= N1 * (ZKP - 2*Hn)) return;
    int m = idx / (ZKP - 2*Hn);
    int d = idx % (ZKP - 2*Hn);
    float v = (d < Pn) ? spe[(size_t)seg[m] * Pn + d] : 0.f;
    bf16 h, l;
    split_bf16(v, h, l);
    g_z2hi[(size_t)m * ZKP + 2*Hn + d] = h;
    g_z2lo[(size_t)m * ZKP + 2*Hn + d] = l;
}

// ---------------- classifier head ------------------------------------------------
__global__ void final_dense_kernel(const float* __restrict__ dW,
                                   const float* __restrict__ db,
                                   float* __restrict__ outp)
{
    __shared__ float r0[128];
    __shared__ float r1[128];
    __shared__ float r2[128];
    int b = blockIdx.x;
    int tid = threadIdx.x;
    float a0 = 0.f, a1 = 0.f, a2 = 0.f;
    for (int k = tid; k < 4*Hn; k += 128) {
        float f;
        if (k < 2*Hn)      f = d_docvec[b * 2*Hn + k];
        else if (k < 3*Hn) f = d_hT[(0 * Bn + b) * Hn + (k - 2*Hn)];
        else               f = d_hT[(1 * Bn + b) * Hn + (k - 3*Hn)];
        a0 += f * dW[0*4*Hn + k];
        a1 += f * dW[1*4*Hn + k];
        a2 += f * dW[2*4*Hn + k];
    }
    r0[tid] = a0;
    r1[tid] = a1;
    r2[tid] = a2;
    __syncthreads();
    for (int s = 64; s > 0; s >>= 1) {
        if (tid < s) {
            r0[tid] += r0[tid+s];
            r1[tid] += r1[tid+s];
            r2[tid] += r2[tid+s];
        }
        __syncthreads();
    }
    if (tid == 0) {
        outp[b*3+0] = r0[0] + db[0];
        outp[b*3+1] = r1[0] + db[1];
        outp[b*3+2] = r2[0] + db[2];
    }
}

// ---------------- host driver ------------------------------------------------------
extern "C" void kernel_launch(void* const* d_in, const int* in_sizes, int n_in,
                              void* d_out, int out_size)
{
    const int*   tok     = (const int*)d_in[0];
    const int*   wpos    = (const int*)d_in[1];
    const int*   seg     = (const int*)d_in[2];
    const float* emb     = (const float*)d_in[3];
    const float* wpe     = (const float*)d_in[4];
    const float* spe     = (const float*)d_in[5];
    const float* wWih_f  = (const float*)d_in[6];
    const float* wWhh_f  = (const float*)d_in[7];
    const float* wb_f    = (const float*)d_in[8];
    const float* wWih_b  = (const float*)d_in[9];
    const float* wWhh_b  = (const float*)d_in[10];
    const float* wb_b    = (const float*)d_in[11];
    const float* sWih_f  = (const float*)d_in[12];
    const float* sWhh_f  = (const float*)d_in[13];
    const float* sb_f    = (const float*)d_in[14];
    const float* sWih_b  = (const float*)d_in[15];
    const float* sWhh_b  = (const float*)d_in[16];
    const float* sb_b    = (const float*)d_in[17];
    const float* word_W  = (const float*)d_in[18];
    const float* word_b  = (const float*)d_in[19];
    const float* word_p  = (const float*)d_in[20];
    const float* sent_W  = (const float*)d_in[21];
    const float* sent_b  = (const float*)d_in[22];
    const float* sent_p  = (const float*)d_in[23];
    const float* dense_W = (const float*)d_in[24];
    const float* dense_b = (const float*)d_in[25];
    float* outp = (float*)d_out;

    float *pgpre, *pz, *pscp, *psc, *psenvec, *pgpre2, *pz2,
          *phT, *pscp2, *psc2, *pdocvec, *pwtf, *pwtb, *pstf, *pstb;
    bf16 *pxhi, *pxlo, *pzhi, *pzlo, *psxhi, *psxlo, *pz2hi, *pz2lo,
         *pwihfh, *pwihfl, *pwihbh, *pwihbl, *psihfh, *psihfl, *psihbh, *psihbl,
         *pwWth, *pwWtl, *psWth, *psWtl;
    cudaGetSymbolAddress((void**)&pgpre,   d_gpre);
    cudaGetSymbolAddress((void**)&pz,      d_z);
    cudaGetSymbolAddress((void**)&pscp,    d_scp);
    cudaGetSymbolAddress((void**)&psc,     d_scores);
    cudaGetSymbolAddress((void**)&psenvec, d_senvec);
    cudaGetSymbolAddress((void**)&pgpre2,  d_gpre2);
    cudaGetSymbolAddress((void**)&pz2,     d_z2);
    cudaGetSymbolAddress((void**)&phT,     d_hT);
    cudaGetSymbolAddress((void**)&pscp2,   d_scp2);
    cudaGetSymbolAddress((void**)&psc2,    d_scores2);
    cudaGetSymbolAddress((void**)&pdocvec, d_docvec);
    cudaGetSymbolAddress((void**)&pwtf,    d_wtf);
    cudaGetSymbolAddress((void**)&pwtb,    d_wtb);
    cudaGetSymbolAddress((void**)&pstf,    d_stf);
    cudaGetSymbolAddress((void**)&pstb,    d_stb);
    cudaGetSymbolAddress((void**)&pxhi,    g_xhi);
    cudaGetSymbolAddress((void**)&pxlo,    g_xlo);
    cudaGetSymbolAddress((void**)&pzhi,    g_zhi);
    cudaGetSymbolAddress((void**)&pzlo,    g_zlo);
    cudaGetSymbolAddress((void**)&psxhi,   g_sxhi);
    cudaGetSymbolAddress((void**)&psxlo,   g_sxlo);
    cudaGetSymbolAddress((void**)&pz2hi,   g_z2hi);
    cudaGetSymbolAddress((void**)&pz2lo,   g_z2lo);
    cudaGetSymbolAddress((void**)&pwihfh,  g_wihf_hi);
    cudaGetSymbolAddress((void**)&pwihfl,  g_wihf_lo);
    cudaGetSymbolAddress((void**)&pwihbh,  g_wihb_hi);
    cudaGetSymbolAddress((void**)&pwihbl,  g_wihb_lo);
    cudaGetSymbolAddress((void**)&psihfh,  g_sihf_hi);
    cudaGetSymbolAddress((void**)&psihfl,  g_sihf_lo);
    cudaGetSymbolAddress((void**)&psihbh,  g_sihb_hi);
    cudaGetSymbolAddress((void**)&psihbl,  g_sihb_lo);
    cudaGetSymbolAddress((void**)&pwWth,   g_wWt_hi);
    cudaGetSymbolAddress((void**)&pwWtl,   g_wWt_lo);
    cudaGetSymbolAddress((void**)&psWth,   g_sWt_hi);
    cudaGetSymbolAddress((void**)&psWtl,   g_sWt_lo);

    cudaFuncSetAttribute(lstm_scan_w, cudaFuncAttributeMaxDynamicSharedMemorySize,
                         2*8*1024*4 + 256*8*4);
    cudaFuncSetAttribute(lstm_scan_s, cudaFuncAttributeMaxDynamicSharedMemorySize,
                         2*8*1024*4 + 256*4);
    cudaFuncSetAttribute(gemm_wb, cudaFuncAttributeMaxDynamicSharedMemorySize,
                         GEMM_SMEM2);

    // 1. gather + padding
    gather_x_kernel<<<(M1*DIN1 + 255)/256, 256>>>(tok, wpos, emb, wpe);
    pad_x_kernel<<<(M1*(XKP-DIN1) + 255)/256, 256>>>();
    pad_z_kernel<<<(M1*(ZKP-DATT) + 255)/256, 256>>>();

    // 2. weight conversions + Whh transposes
    conv_pad<<<(Gn*XKP + 255)/256, 256>>>(wWih_f, pwihfh, pwihfl, Gn, DIN1, XKP);
    conv_pad<<<(Gn*XKP + 255)/256, 256>>>(wWih_b, pwihbh, pwihbl, Gn, DIN1, XKP);
    conv_pad<<<(Gn*ZKP + 255)/256, 256>>>(sWih_f, psihfh, psihfl, Gn, DATT, ZKP);
    conv_pad<<<(Gn*ZKP + 255)/256, 256>>>(sWih_b, psihbh, psihbl, Gn, DATT, ZKP);
    conv_wt<<<(ZKP*ZKP + 255)/256, 256>>>(word_W, pwWth, pwWtl, DATT, ZKP, ZKP);
    conv_wt<<<(ZKP*ZKP + 255)/256, 256>>>(sent_W, psWth, psWtl, DATT, ZKP, ZKP);
    transpose_k<<<(Gn*Hn + 255)/256, 256>>>(wWhh_f, pwtf, Gn, Hn);
    transpose_k<<<(Gn*Hn + 255)/256, 256>>>(wWhh_b, pwtb, Gn, Hn);
    transpose_k<<<(Gn*Hn + 255)/256, 256>>>(sWhh_f, pstf, Gn, Hn);
    transpose_k<<<(Gn*Hn + 255)/256, 256>>>(sWhh_b, pstb, Gn, Hn);

    // 3. word input GEMMs
    {
        dim3 g(Gn/64, M1/128);
        gemm_wb<<<g, 256, GEMM_SMEM2>>>(pxhi, pxlo, pwihfh, pwihfl, wb_f, (const float*)0,
                                        pgpre, M1, Gn, XKP, Gn, 0);
        gemm_wb<<<g, 256, GEMM_SMEM2>>>(pxhi, pxlo, pwihbh, pwihbl, wb_b, (const float*)0,
                                        pgpre + (size_t)M1*Gn, M1, Gn, XKP, Gn, 0);
    }

    // 4. word BiLSTM scan -> d_z fp32 + z bf16
    lstm_scan_w<<<128, 256, 2*8*1024*4 + 256*8*4>>>(pgpre, pwtf, pwtb, pz,
                                                    pzhi, pzlo, N1, Ln, DATT);

    // 5. word attention
    gemm_wb<<<dim3(NBATT, M1/128), 256, GEMM_SMEM2>>>(pzhi, pzlo, pwWth, pwWtl,
                                                      word_b, word_p, pscp,
                                                      M1, ZKP, ZKP, DATT, 1);
    sum_scores<<<(M1 + 255)/256, 256>>>(pscp, psc, M1, NBATT);
    softmax_pool_kernel<<<N1, 256>>>(psc, pz, psenvec, Ln, DATT);

    // 6. sentence input
    build_sx_kernel<<<(N1*ZKP + 255)/256, 256>>>(seg, spe);
    fill_z2pos<<<(N1*(ZKP-2*Hn) + 255)/256, 256>>>(seg, spe);
    {
        dim3 g(Gn/64, N1/128);
        gemm_wb<<<g, 256, GEMM_SMEM2>>>(psxhi, psxlo, psihfh, psihfl, sb_f, (const float*)0,
                                        pgpre2, N1, Gn, ZKP, Gn, 0);
        gemm_wb<<<g, 256, GEMM_SMEM2>>>(psxhi, psxlo, psihbh, psihbl, sb_b, (const float*)0,
                                        pgpre2 + (size_t)N1*Gn, N1, Gn, ZKP, Gn, 0);
    }

    // 7. sentence BiLSTM scan -> d_z2 fp32 + z2 bf16, keeps hT
    lstm_scan_s<<<2*Bn, 256, 2*8*1024*4 + 256*4>>>(pgpre2, pstf, pstb, pz2,
                                                   pz2hi, pz2lo, phT, Bn, Sn, DATT);

    // 8. sentence attention
    gemm_wb<<<dim3(NBATT, N1/128), 256, GEMM_SMEM2>>>(pz2hi, pz2lo, psWth, psWtl,
                                                      sent_b, sent_p, pscp2,
                                                      N1, ZKP, ZKP, DATT, 1);
    sum_scores<<<(N1 + 255)/256, 256>>>(pscp2, psc2, N1, NBATT);
    softmax_pool_kernel<<<Bn, 256>>>(psc2, pz2, pdocvec, Sn, DATT);

    // 9. classifier head
    final_dense_kernel<<<Bn, 128>>>(dense_W, dense_b, outp);
}

// round 9
// speedup vs baseline: 1.5565x; 1.2475x over previous
#include <cuda_runtime.h>
#include <cuda_bf16.h>
#include <mma.h>
#include <cstdint>
#include <math.h>

using namespace nvcuda;

// ---------------- problem constants ----------------
#define Bn   32
#define Sn   16
#define Ln   64
#define En   300
#define Pn   100
#define Hn   256
#define Gn   1024
#define DATT 612
#define N1   (Bn*Sn)
#define M1   (N1*Ln)
#define DIN1 (En+Pn)
#define NBATT 5             // 640/128
#define XKP  416            // padded K for x (400)
#define ZKP  640            // padded K/N for 612

typedef unsigned long long u64;
typedef __nv_bfloat16 bf16;

// ---------------- scratch (device globals) ----------------------------------
__device__ float d_gpre[2*M1*Gn];
__device__ float d_z[M1*DATT];
__device__ float d_scp[M1*NBATT];
__device__ float d_scores[M1];
__device__ float d_senvec[N1*2*Hn];
__device__ float d_gpre2[2*N1*Gn];
__device__ float d_z2[N1*DATT];
__device__ float d_hT[2*Bn*Hn];
__device__ float d_scp2[N1*NBATT];
__device__ float d_scores2[N1];
__device__ float d_docvec[Bn*2*Hn];
__device__ float d_wtf[Hn*Gn];
__device__ float d_wtb[Hn*Gn];
__device__ float d_stf[Hn*Gn];
__device__ float d_stb[Hn*Gn];
__device__ bf16 g_xhi[M1*XKP];
__device__ bf16 g_xlo[M1*XKP];
__device__ bf16 g_zhi[(size_t)M1*ZKP];
__device__ bf16 g_zlo[(size_t)M1*ZKP];
__device__ bf16 g_sxhi[N1*ZKP];
__device__ bf16 g_sxlo[N1*ZKP];
__device__ bf16 g_z2hi[N1*ZKP];
__device__ bf16 g_z2lo[N1*ZKP];
__device__ bf16 g_wihf_hi[Gn*XKP];
__device__ bf16 g_wihf_lo[Gn*XKP];
__device__ bf16 g_wihb_hi[Gn*XKP];
__device__ bf16 g_wihb_lo[Gn*XKP];
__device__ bf16 g_sihf_hi[Gn*ZKP];
__device__ bf16 g_sihf_lo[Gn*ZKP];
__device__ bf16 g_sihb_hi[Gn*ZKP];
__device__ bf16 g_sihb_lo[Gn*ZKP];
__device__ bf16 g_wWt_hi[ZKP*ZKP];
__device__ bf16 g_wWt_lo[ZKP*ZKP];
__device__ bf16 g_sWt_hi[ZKP*ZKP];
__device__ bf16 g_sWt_lo[ZKP*ZKP];

__device__ __forceinline__ float sigmoidf(float x) { return 1.0f / (1.0f + expf(-x)); }

__device__ __forceinline__ void fma2(u64& d, u64 a, u64 b) {
    asm("fma.rn.f32x2 %0, %1, %2, %3;" : "=l"(d) : "l"(a), "l"(b), "l"(d));
}
__device__ __forceinline__ u64 pack2(float x, float y) {
    u64 r; asm("mov.b64 %0, {%1,%2};" : "=l"(r) : "f"(x), "f"(y)); return r;
}
__device__ __forceinline__ void unpack2(float& lo, float& hi, u64 v) {
    asm("mov.b64 {%0,%1}, %2;" : "=f"(lo), "=f"(hi) : "l"(v));
}
__device__ __forceinline__ void split_bf16(float v, bf16& h, bf16& l) {
    h = __float2bfloat16(v);
    l = __float2bfloat16(v - __bfloat162float(h));
}
__device__ __forceinline__ uint32_t smem_u32(const void* p) {
    return (uint32_t)__cvta_generic_to_shared(p);
}
__device__ __forceinline__ void cp16(uint32_t dst, const void* src) {
    asm volatile("cp.async.cg.shared.global [%0], [%1], 16;" :: "r"(dst), "l"(src));
}
#define CP_COMMIT() asm volatile("cp.async.commit_group;" ::: "memory")
#define CP_WAIT0()  asm volatile("cp.async.wait_group 0;" ::: "memory")

// ======================= WMMA split-bf16 GEMM, 128x128 tile ==================
// C[M,Nc] = A[M,KP] @ B[*,KP]^T, pre-split bf16 hi/lo, KP mult of 32,
// M mult 128, Nc mult 128. cp.async double buffer, K-step 32.
// attn==0: C[m*Nc+n] = acc + bias[n]
// attn!=0: C[m*gridDim.x + bx] = sum_{n<Nv} tanh(acc+bias[n])*proj[n]
// smem: 2 stages x (Ah|Al|Bh|Bl each 128x32 bf16 8192B) = 65536B; epilogue
// reuses as 128x128 f32 out tile; red[256] at +65536.
#define GEMM_SMEM2 66560

__global__ __launch_bounds__(256)
void gemm_wb(const bf16* __restrict__ Ahi, const bf16* __restrict__ Alo,
             const bf16* __restrict__ Bhi, const bf16* __restrict__ Blo,
             const float* __restrict__ bias, const float* __restrict__ proj,
             float* __restrict__ C, int M, int Nc, int KP, int Nv, int attn)
{
    extern __shared__ float dynsm[];
    bf16* sb    = (bf16*)dynsm;      // staged tiles
    float* outs = dynsm;             // reused after mainloop
    float* red  = dynsm + 16384;     // byte 65536

    const int tid = threadIdx.x;
    const int m0 = blockIdx.y * 128;
    const int n0 = blockIdx.x * 128;
    const int w  = tid >> 5;
    const int wm = w >> 1;           // 0..3  (32-row band)
    const int wn = w & 1;            // 0..1  (64-col band)

    wmma::fragment<wmma::accumulator, 16, 16, 16, float> acc[2][4];
#pragma unroll
    for (int i = 0; i < 2; i++)
#pragma unroll
        for (int j = 0; j < 4; j++)
            wmma::fill_fragment(acc[i][j], 0.0f);

    const int nk   = KP / 32;
    const int rowi = tid >> 1;               // 0..127
    const int kof  = (tid & 1) * 16;         // bf16 elems
    const uint32_t sbase = smem_u32(sb);
    const uint32_t boff  = (uint32_t)(rowi * 64 + kof * 2);   // bytes in tile

    const bf16* __restrict__ pah = Ahi + (size_t)(m0 + rowi) * KP + kof;
    const bf16* __restrict__ pal = Alo + (size_t)(m0 + rowi) * KP + kof;
    const bf16* __restrict__ pbh = Bhi + (size_t)(n0 + rowi) * KP + kof;
    const bf16* __restrict__ pbl = Blo + (size_t)(n0 + rowi) * KP + kof;

    // issue stage for chunk kc into buffer s
    // (Ah @ +0, Al @ +8192, Bh @ +16384, Bl @ +24576 bytes; stage stride 32768)
    {
        const uint32_t d0 = sbase + boff;
        cp16(d0 +     0, pah);     cp16(d0 +    16, pah + 8);
        cp16(d0 +  8192, pal);     cp16(d0 +  8192 + 16, pal + 8);
        cp16(d0 + 16384, pbh);     cp16(d0 + 16384 + 16, pbh + 8);
        cp16(d0 + 24576, pbl);     cp16(d0 + 24576 + 16, pbl + 8);
        CP_COMMIT();
        CP_WAIT0();
    }
    __syncthreads();

    for (int kc = 0; kc < nk; kc++) {
        const int cur = kc & 1;
        if (kc + 1 < nk) {
            const int go = (kc + 1) * 32;
            const uint32_t d1 = sbase + (uint32_t)((cur ^ 1) * 32768) + boff;
            cp16(d1 +     0, pah + go);     cp16(d1 +    16, pah + go + 8);
            cp16(d1 +  8192, pal + go);     cp16(d1 +  8192 + 16, pal + go + 8);
            cp16(d1 + 16384, pbh + go);     cp16(d1 + 16384 + 16, pbh + go + 8);
            cp16(d1 + 24576, pbl + go);     cp16(d1 + 24576 + 16, pbl + go + 8);
            CP_COMMIT();
        }
        const bf16* Ah = sb + cur * 16384;
        const bf16* Al = Ah + 4096;
        const bf16* Bh = Ah + 8192;
        const bf16* Bl = Ah + 12288;
#pragma unroll
        for (int kf = 0; kf < 2; kf++) {
            wmma::fragment<wmma::matrix_a, 16, 16, 16, bf16, wmma::row_major> ah[2], al[2];
            wmma::fragment<wmma::matrix_b, 16, 16, 16, bf16, wmma::col_major> bh[4], bl[4];
#pragma unroll
            for (int i = 0; i < 2; i++) {
                wmma::load_matrix_sync(ah[i], Ah + (wm*32 + i*16)*32 + kf*16, 32);
                wmma::load_matrix_sync(al[i], Al + (wm*32 + i*16)*32 + kf*16, 32);
            }
#pragma unroll
            for (int j = 0; j < 4; j++) {
                wmma::load_matrix_sync(bh[j], Bh + (wn*64 + j*16)*32 + kf*16, 32);
                wmma::load_matrix_sync(bl[j], Bl + (wn*64 + j*16)*32 + kf*16, 32);
            }
#pragma unroll
            for (int i = 0; i < 2; i++) {
#pragma unroll
                for (int j = 0; j < 4; j++) {
                    wmma::mma_sync(acc[i][j], ah[i], bh[j], acc[i][j]);
                    wmma::mma_sync(acc[i][j], ah[i], bl[j], acc[i][j]);
                    wmma::mma_sync(acc[i][j], al[i], bh[j], acc[i][j]);
                }
            }
        }
        if (kc + 1 < nk) CP_WAIT0();
        __syncthreads();
    }

    // epilogue: reuse smem as fp32 out tile [128][128]
#pragma unroll
    for (int i = 0; i < 2; i++)
#pragma unroll
        for (int j = 0; j < 4; j++)
            wmma::store_matrix_sync(outs + (size_t)(wm*32 + i*16)*128 + wn*64 + j*16,
                                    acc[i][j], 128, wmma::mem_row_major);
    __syncthreads();

    if (attn == 0) {
        for (int i = tid; i < 128*128; i += 256) {
            int row = i >> 7;
            int col = i & 127;
            C[(size_t)(m0 + row) * Nc + n0 + col] = outs[i] + bias[n0 + col];
        }
    } else {
        const int row = tid >> 1;
        const int hf  = (tid & 1) * 64;
        float part = 0.f;
#pragma unroll
        for (int c = 0; c < 64; c++) {
            int n = n0 + hf + c;
            if (n < Nv) part += tanhf(outs[row*128 + hf + c] + bias[n]) * proj[n];
        }
        red[tid] = part;
        __syncthreads();
        if (tid < 128) {
            C[(size_t)(m0 + tid) * gridDim.x + blockIdx.x] = red[2*tid] + red[2*tid + 1];
        }
    }
}

// ---------------- gather: x bf16 hi/lo + z pos cols bf16 ----------------------
__global__ void gather_x_kernel(const int* __restrict__ tok,
                                const int* __restrict__ wpos,
                                const float* __restrict__ emb,
                                const float* __restrict__ wpe)
{
    int idx = blockIdx.x * blockDim.x + threadIdx.x;
    if (idx >= M1 * DIN1) return;
    int d = idx % DIN1;
    int m = idx / DIN1;
    float v;
    if (d < En) {
        v = emb[(size_t)tok[m] * En + d];
    } else {
        v = wpe[(size_t)wpos[m] * Pn + (d - En)];
        bf16 h, l;
        split_bf16(v, h, l);
        size_t zi = (size_t)m * ZKP + 2*Hn + (d - En);
        g_zhi[zi] = h;
        g_zlo[zi] = l;
    }
    bf16 h, l;
    split_bf16(v, h, l);
    g_xhi[(size_t)m * XKP + d] = h;
    g_xlo[(size_t)m * XKP + d] = l;
}

__global__ void pad_x_kernel()
{
    int idx = blockIdx.x * blockDim.x + threadIdx.x;
    if (idx >= M1 * (XKP - DIN1)) return;
    int m = idx / (XKP - DIN1);
    int k = DIN1 + idx % (XKP - DIN1);
    g_xhi[(size_t)m * XKP + k] = __float2bfloat16(0.f);
    g_xlo[(size_t)m * XKP + k] = __float2bfloat16(0.f);
}

__global__ void pad_z_kernel()
{
    int idx = blockIdx.x * blockDim.x + threadIdx.x;
    if (idx >= M1 * (ZKP - DATT)) return;
    int m = idx / (ZKP - DATT);
    int k = DATT + idx % (ZKP - DATT);
    g_zhi[(size_t)m * ZKP + k] = __float2bfloat16(0.f);
    g_zlo[(size_t)m * ZKP + k] = __float2bfloat16(0.f);
}

// ---------------- weight conversions -------------------------------------------
__global__ void conv_pad(const float* __restrict__ W, bf16* __restrict__ hi,
                         bf16* __restrict__ lo, int rows, int kc, int kp)
{
    int idx = blockIdx.x * blockDim.x + threadIdx.x;
    if (idx >= rows * kp) return;
    int r = idx / kp;
    int k = idx % kp;
    float v = (k < kc) ? W[(size_t)r * kc + k] : 0.f;
    bf16 h, l;
    split_bf16(v, h, l);
    hi[idx] = h;
    lo[idx] = l;
}

__global__ void conv_wt(const float* __restrict__ W, bf16* __restrict__ hi,
                        bf16* __restrict__ lo, int d, int np, int kp)
{
    int idx = blockIdx.x * blockDim.x + threadIdx.x;
    if (idx >= np * kp) return;
    int e = idx / kp;
    int k = idx % kp;
    float v = (e < d && k < d) ? W[(size_t)k * d + e] : 0.f;
    bf16 h, l;
    split_bf16(v, h, l);
    hi[idx] = h;
    lo[idx] = l;
}

// ---------------- transpose (Whh for scans) -------------------------------------
__global__ void transpose_k(const float* __restrict__ W, float* __restrict__ Wt,
                            int Gr, int Kc)
{
    int idx = blockIdx.x * blockDim.x + threadIdx.x;
    if (idx >= Gr * Kc) return;
    int g = idx / Kc;
    int k = idx % Kc;
    Wt[(size_t)k * Gr + g] = W[idx];
}

// ---------------- word BiLSTM scan (8 rows/block) ------------------------------
__global__ __launch_bounds__(256, 1)
void lstm_scan_w(const float* __restrict__ gpre,
                 const float* __restrict__ Wt_f,
                 const float* __restrict__ Wt_b,
                 float* __restrict__ out,
                 bf16* __restrict__ zhi, bf16* __restrict__ zlo,
                 int N, int T, int ostride)
{
    extern __shared__ float dynsm[];
    float* ws = dynsm;
    float* hs = dynsm + 2*8*1024;
    const int tid = threadIdx.x;
    const int nb  = N / 8;
    const int dir = blockIdx.x / nb;
    const int n0  = (blockIdx.x % nb) * 8;
    const float* __restrict__ Wt = dir ? Wt_b : Wt_f;

    float c[8];
#pragma unroll
    for (int r = 0; r < 8; r++) c[r] = 0.f;
    for (int i = tid; i < 256*8; i += 256) hs[i] = 0.f;

#pragma unroll
    for (int i = 0; i < 8; i++) {
        *(float4*)&ws[(tid + 256*i)*4] = *(const float4*)&Wt[(tid + 256*i)*4];
    }
    __syncthreads();

    const int NT = 32;
    for (int step = 0; step < T; step++) {
        const int tt = dir ? (T - 1 - step) : step;
        u64 acc2[4][4];
#pragma unroll
        for (int rp = 0; rp < 4; rp++) {
            size_t b0 = ((size_t)(dir*N + n0 + rp*2    ) * T + tt) * Gn;
            size_t b1 = ((size_t)(dir*N + n0 + rp*2 + 1) * T + tt) * Gn;
#pragma unroll
            for (int g = 0; g < 4; g++) {
                acc2[rp][g] = pack2(gpre[b0 + g*256 + tid], gpre[b1 + g*256 + tid]);
            }
        }
        for (int kt = 0; kt < NT; kt++) {
            const int cur = kt & 1;
            const bool last = (step == T-1) && (kt == NT-1);
            float4 pf[8];
            if (!last) {
                const float* src = &Wt[(size_t)((kt + 1) & 31) * 8192];
#pragma unroll
                for (int i = 0; i < 8; i++) {
                    pf[i] = *(const float4*)&src[(tid + 256*i)*4];
                }
            }
#pragma unroll
            for (int kk = 0; kk < 8; kk++) {
                const int k = kt*8 + kk;
                const float* wrow = &ws[(cur*8 + kk)*1024];
                float w0 = wrow[tid];
                float w1 = wrow[256+tid];
                float w2 = wrow[512+tid];
                float w3 = wrow[768+tid];
                u64 wd0 = pack2(w0,w0);
                u64 wd1 = pack2(w1,w1);
                u64 wd2 = pack2(w2,w2);
                u64 wd3 = pack2(w3,w3);
#pragma unroll
                for (int rp = 0; rp < 4; rp++) {
                    u64 h2 = *(const u64*)&hs[k*8 + rp*2];
                    fma2(acc2[rp][0], h2, wd0);
                    fma2(acc2[rp][1], h2, wd1);
                    fma2(acc2[rp][2], h2, wd2);
                    fma2(acc2[rp][3], h2, wd3);
                }
            }
            if (!last) {
                float* dst = &ws[(cur ^ 1) * 8192];
#pragma unroll
                for (int i = 0; i < 8; i++) {
                    *(float4*)&dst[(tid + 256*i)*4] = pf[i];
                }
            }
            __syncthreads();
        }
#pragma unroll
        for (int rp = 0; rp < 4; rp++) {
            float p0[2];
            float p1[2];
            float p2[2];
            float p3[2];
            unpack2(p0[0], p0[1], acc2[rp][0]);
            unpack2(p1[0], p1[1], acc2[rp][1]);
            unpack2(p2[0], p2[1], acc2[rp][2]);
            unpack2(p3[0], p3[1], acc2[rp][3]);
#pragma unroll
            for (int hh = 0; hh < 2; hh++) {
                int r = rp*2 + hh;
                float iv = sigmoidf(p0[hh]);
                float fv = sigmoidf(p1[hh]);
                float gv = tanhf(p2[hh]);
                float ov = sigmoidf(p3[hh]);
                c[r] = fv * c[r] + iv * gv;
                float hv = ov * tanhf(c[r]);
                hs[tid*8 + r] = hv;
                size_t mrow = (size_t)(n0 + r) * T + tt;
                out[mrow * ostride + dir*256 + tid] = hv;
                bf16 bh, bl;
                split_bf16(hv, bh, bl);
                zhi[mrow * ZKP + dir*256 + tid] = bh;
                zlo[mrow * ZKP + dir*256 + tid] = bl;
            }
        }
        __syncthreads();
    }
}

// ---------------- sentence BiLSTM scan (1 row/block, keeps hT) ------------------
__global__ __launch_bounds__(256, 1)
void lstm_scan_s(const float* __restrict__ gpre,
                 const float* __restrict__ Wt_f,
                 const float* __restrict__ Wt_b,
                 float* __restrict__ out,
                 bf16* __restrict__ zhi, bf16* __restrict__ zlo,
                 float* __restrict__ hT,
                 int N, int T, int ostride)
{
    extern __shared__ float dynsm[];
    float* ws = dynsm;
    float* hs = dynsm + 2*8*1024;
    const int tid = threadIdx.x;
    const int dir = blockIdx.x / N;
    const int n0  = blockIdx.x % N;
    const float* __restrict__ Wt = dir ? Wt_b : Wt_f;

    float c0 = 0.f;
    hs[tid] = 0.f;

#pragma unroll
    for (int i = 0; i < 8; i++) {
        *(float4*)&ws[(tid + 256*i)*4] = *(const float4*)&Wt[(tid + 256*i)*4];
    }
    __syncthreads();

    const int NT = 32;
    for (int step = 0; step < T; step++) {
        const int tt = dir ? (T - 1 - step) : step;
        float acc[4];
        size_t b0 = ((size_t)(dir*N + n0) * T + tt) * Gn;
#pragma unroll
        for (int g = 0; g < 4; g++) {
            acc[g] = gpre[b0 + g*256 + tid];
        }
        for (int kt = 0; kt < NT; kt++) {
            const int cur = kt & 1;
            const bool last = (step == T-1) && (kt == NT-1);
            float4 pf[8];
            if (!last) {
                const float* src = &Wt[(size_t)((kt + 1) & 31) * 8192];
#pragma unroll
                for (int i = 0; i < 8; i++) {
                    pf[i] = *(const float4*)&src[(tid + 256*i)*4];
                }
            }
#pragma unroll
            for (int kk = 0; kk < 8; kk++) {
                const int k = kt*8 + kk;
                const float* wrow = &ws[(cur*8 + kk)*1024];
                float hv = hs[k];
                acc[0] += hv * wrow[tid];
                acc[1] += hv * wrow[256+tid];
                acc[2] += hv * wrow[512+tid];
                acc[3] += hv * wrow[768+tid];
            }
            if (!last) {
                float* dst = &ws[(cur ^ 1) * 8192];
#pragma unroll
                for (int i = 0; i < 8; i++) {
                    *(float4*)&dst[(tid + 256*i)*4] = pf[i];
                }
            }
            __syncthreads();
        }
        float iv = sigmoidf(acc[0]);
        float fv = sigmoidf(acc[1]);
        float gv = tanhf(acc[2]);
        float ov = sigmoidf(acc[3]);
        c0 = fv * c0 + iv * gv;
        float hv = ov * tanhf(c0);
        hs[tid] = hv;
        size_t mrow = (size_t)n0 * T + tt;
        out[mrow * ostride + dir*256 + tid] = hv;
        bf16 bh, bl;
        split_bf16(hv, bh, bl);
        zhi[mrow * ZKP + dir*256 + tid] = bh;
        zlo[mrow * ZKP + dir*256 + tid] = bl;
        if (step == T - 1) {
            hT[((size_t)dir * N + n0) * 256 + tid] = hv;
        }
        __syncthreads();
    }
}

// ---------------- attention glue -----------------------------------------------
__global__ void sum_scores(const float* __restrict__ scp, float* __restrict__ sc,
                           int M, int NB)
{
    int m = blockIdx.x * blockDim.x + threadIdx.x;
    if (m >= M) return;
    float s = 0.f;
    for (int j = 0; j < NB; j++) s += scp[(size_t)m * NB + j];
    sc[m] = s;
}

__global__ void softmax_pool_kernel(const float* __restrict__ sc,
                                    const float* __restrict__ hsrc,
                                    float* __restrict__ outv,
                                    int T, int stride)
{
    __shared__ float a[64];
    __shared__ float inv_s;
    int n = blockIdx.x;
    int tid = threadIdx.x;
    if (tid == 0) {
        float mx = -1e30f;
        for (int t = 0; t < T; t++) mx = fmaxf(mx, sc[n * T + t]);
        float sum = 0.f;
        for (int t = 0; t < T; t++) {
            float e = expf(sc[n * T + t] - mx);
            a[t] = e;
            sum += e;
        }
        inv_s = 1.f / sum;
    }
    __syncthreads();
    float inv = inv_s;
    for (int col = tid; col < 2*Hn; col += blockDim.x) {
        float acc = 0.f;
        for (int t = 0; t < T; t++) {
            acc += a[t] * hsrc[((size_t)n * T + t) * stride + col];
        }
        outv[(size_t)n * (2*Hn) + col] = acc * inv;
    }
}

__global__ void build_sx_kernel(const int* __restrict__ seg,
                                const float* __restrict__ spe)
{
    int idx = blockIdx.x * blockDim.x + threadIdx.x;
    if (idx >= N1 * ZKP) return;
    int d = idx % ZKP;
    int m = idx / ZKP;
    float v;
    if (d < 2*Hn)      v = d_senvec[(size_t)m * (2*Hn) + d];
    else if (d < DATT) v = spe[(size_t)seg[m] * Pn + (d - 2*Hn)];
    else               v = 0.f;
    bf16 h, l;
    split_bf16(v, h, l);
    g_sxhi[idx] = h;
    g_sxlo[idx] = l;
}

__global__ void fill_z2pos(const int* __restrict__ seg, const float* __restrict__ spe)
{
    int idx = blockIdx.x * blockDim.x + threadIdx.x;
    if (idx >= N1 * (ZKP - 2*Hn)) return;
    int m = idx / (ZKP - 2*Hn);
    int d = idx % (ZKP - 2*Hn);
    float v = (d < Pn) ? spe[(size_t)seg[m] * Pn + d] : 0.f;
    bf16 h, l;
    split_bf16(v, h, l);
    g_z2hi[(size_t)m * ZKP + 2*Hn + d] = h;
    g_z2lo[(size_t)m * ZKP + 2*Hn + d] = l;
}

// ---------------- classifier head ------------------------------------------------
__global__ void final_dense_kernel(const float* __restrict__ dW,
                                   const float* __restrict__ db,
                                   float* __restrict__ outp)
{
    __shared__ float r0[128];
    __shared__ float r1[128];
    __shared__ float r2[128];
    int b = blockIdx.x;
    int tid = threadIdx.x;
    float a0 = 0.f, a1 = 0.f, a2 = 0.f;
    for (int k = tid; k < 4*Hn; k += 128) {
        float f;
        if (k < 2*Hn)      f = d_docvec[b * 2*Hn + k];
        else if (k < 3*Hn) f = d_hT[(0 * Bn + b) * Hn + (k - 2*Hn)];
        else               f = d_hT[(1 * Bn + b) * Hn + (k - 3*Hn)];
        a0 += f * dW[0*4*Hn + k];
        a1 += f * dW[1*4*Hn + k];
        a2 += f * dW[2*4*Hn + k];
    }
    r0[tid] = a0;
    r1[tid] = a1;
    r2[tid] = a2;
    __syncthreads();
    for (int s = 64; s > 0; s >>= 1) {
        if (tid < s) {
            r0[tid] += r0[tid+s];
            r1[tid] += r1[tid+s];
            r2[tid] += r2[tid+s];
        }
        __syncthreads();
    }
    if (tid == 0) {
        outp[b*3+0] = r0[0] + db[0];
        outp[b*3+1] = r1[0] + db[1];
        outp[b*3+2] = r2[0] + db[2];
    }
}

// ---------------- host driver ------------------------------------------------------
extern "C" void kernel_launch(void* const* d_in, const int* in_sizes, int n_in,
                              void* d_out, int out_size)
{
    const int*   tok     = (const int*)d_in[0];
    const int*   wpos    = (const int*)d_in[1];
    const int*   seg     = (const int*)d_in[2];
    const float* emb     = (const float*)d_in[3];
    const float* wpe     = (const float*)d_in[4];
    const float* spe     = (const float*)d_in[5];
    const float* wWih_f  = (const float*)d_in[6];
    const float* wWhh_f  = (const float*)d_in[7];
    const float* wb_f    = (const float*)d_in[8];
    const float* wWih_b  = (const float*)d_in[9];
    const float* wWhh_b  = (const float*)d_in[10];
    const float* wb_b    = (const float*)d_in[11];
    const float* sWih_f  = (const float*)d_in[12];
    const float* sWhh_f  = (const float*)d_in[13];
    const float* sb_f    = (const float*)d_in[14];
    const float* sWih_b  = (const float*)d_in[15];
    const float* sWhh_b  = (const float*)d_in[16];
    const float* sb_b    = (const float*)d_in[17];
    const float* word_W  = (const float*)d_in[18];
    const float* word_b  = (const float*)d_in[19];
    const float* word_p  = (const float*)d_in[20];
    const float* sent_W  = (const float*)d_in[21];
    const float* sent_b  = (const float*)d_in[22];
    const float* sent_p  = (const float*)d_in[23];
    const float* dense_W = (const float*)d_in[24];
    const float* dense_b = (const float*)d_in[25];
    float* outp = (float*)d_out;

    float *pgpre, *pz, *pscp, *psc, *psenvec, *pgpre2, *pz2,
          *phT, *pscp2, *psc2, *pdocvec, *pwtf, *pwtb, *pstf, *pstb;
    bf16 *pxhi, *pxlo, *pzhi, *pzlo, *psxhi, *psxlo, *pz2hi, *pz2lo,
         *pwihfh, *pwihfl, *pwihbh, *pwihbl, *psihfh, *psihfl, *psihbh, *psihbl,
         *pwWth, *pwWtl, *psWth, *psWtl;
    cudaGetSymbolAddress((void**)&pgpre,   d_gpre);
    cudaGetSymbolAddress((void**)&pz,      d_z);
    cudaGetSymbolAddress((void**)&pscp,    d_scp);
    cudaGetSymbolAddress((void**)&psc,     d_scores);
    cudaGetSymbolAddress((void**)&psenvec, d_senvec);
    cudaGetSymbolAddress((void**)&pgpre2,  d_gpre2);
    cudaGetSymbolAddress((void**)&pz2,     d_z2);
    cudaGetSymbolAddress((void**)&phT,     d_hT);
    cudaGetSymbolAddress((void**)&pscp2,   d_scp2);
    cudaGetSymbolAddress((void**)&psc2,    d_scores2);
    cudaGetSymbolAddress((void**)&pdocvec, d_docvec);
    cudaGetSymbolAddress((void**)&pwtf,    d_wtf);
    cudaGetSymbolAddress((void**)&pwtb,    d_wtb);
    cudaGetSymbolAddress((void**)&pstf,    d_stf);
    cudaGetSymbolAddress((void**)&pstb,    d_stb);
    cudaGetSymbolAddress((void**)&pxhi,    g_xhi);
    cudaGetSymbolAddress((void**)&pxlo,    g_xlo);
    cudaGetSymbolAddress((void**)&pzhi,    g_zhi);
    cudaGetSymbolAddress((void**)&pzlo,    g_zlo);
    cudaGetSymbolAddress((void**)&psxhi,   g_sxhi);
    cudaGetSymbolAddress((void**)&psxlo,   g_sxlo);
    cudaGetSymbolAddress((void**)&pz2hi,   g_z2hi);
    cudaGetSymbolAddress((void**)&pz2lo,   g_z2lo);
    cudaGetSymbolAddress((void**)&pwihfh,  g_wihf_hi);
    cudaGetSymbolAddress((void**)&pwihfl,  g_wihf_lo);
    cudaGetSymbolAddress((void**)&pwihbh,  g_wihb_hi);
    cudaGetSymbolAddress((void**)&pwihbl,  g_wihb_lo);
    cudaGetSymbolAddress((void**)&psihfh,  g_sihf_hi);
    cudaGetSymbolAddress((void**)&psihfl,  g_sihf_lo);
    cudaGetSymbolAddress((void**)&psihbh,  g_sihb_hi);
    cudaGetSymbolAddress((void**)&psihbl,  g_sihb_lo);
    cudaGetSymbolAddress((void**)&pwWth,   g_wWt_hi);
    cudaGetSymbolAddress((void**)&pwWtl,   g_wWt_lo);
    cudaGetSymbolAddress((void**)&psWth,   g_sWt_hi);
    cudaGetSymbolAddress((void**)&psWtl,   g_sWt_lo);

    cudaFuncSetAttribute(lstm_scan_w, cudaFuncAttributeMaxDynamicSharedMemorySize,
                         2*8*1024*4 + 256*8*4);
    cudaFuncSetAttribute(lstm_scan_s, cudaFuncAttributeMaxDynamicSharedMemorySize,
                         2*8*1024*4 + 256*4);
    cudaFuncSetAttribute(gemm_wb, cudaFuncAttributeMaxDynamicSharedMemorySize,
                         GEMM_SMEM2);

    // 1. gather + padding
    gather_x_kernel<<<(M1*DIN1 + 255)/256, 256>>>(tok, wpos, emb, wpe);
    pad_x_kernel<<<(M1*(XKP-DIN1) + 255)/256, 256>>>();
    pad_z_kernel<<<(M1*(ZKP-DATT) + 255)/256, 256>>>();

    // 2. weight conversions + Whh transposes
    conv_pad<<<(Gn*XKP + 255)/256, 256>>>(wWih_f, pwihfh, pwihfl, Gn, DIN1, XKP);
    conv_pad<<<(Gn*XKP + 255)/256, 256>>>(wWih_b, pwihbh, pwihbl, Gn, DIN1, XKP);
    conv_pad<<<(Gn*ZKP + 255)/256, 256>>>(sWih_f, psihfh, psihfl, Gn, DATT, ZKP);
    conv_pad<<<(Gn*ZKP + 255)/256, 256>>>(sWih_b, psihbh, psihbl, Gn, DATT, ZKP);
    conv_wt<<<(ZKP*ZKP + 255)/256, 256>>>(word_W, pwWth, pwWtl, DATT, ZKP, ZKP);
    conv_wt<<<(ZKP*ZKP + 255)/256, 256>>>(sent_W, psWth, psWtl, DATT, ZKP, ZKP);
    transpose_k<<<(Gn*Hn + 255)/256, 256>>>(wWhh_f, pwtf, Gn, Hn);
    transpose_k<<<(Gn*Hn + 255)/256, 256>>>(wWhh_b, pwtb, Gn, Hn);
    transpose_k<<<(Gn*Hn + 255)/256, 256>>>(sWhh_f, pstf, Gn, Hn);
    transpose_k<<<(Gn*Hn + 255)/256, 256>>>(sWhh_b, pstb, Gn, Hn);

    // 3. word input GEMMs
    {
        dim3 g(Gn/128, M1/128);
        gemm_wb<<<g, 256, GEMM_SMEM2>>>(pxhi, pxlo, pwihfh, pwihfl, wb_f, (const float*)0,
                                        pgpre, M1, Gn, XKP, Gn, 0);
        gemm_wb<<<g, 256, GEMM_SMEM2>>>(pxhi, pxlo, pwihbh, pwihbl, wb_b, (const float*)0,
                                        pgpre + (size_t)M1*Gn, M1, Gn, XKP, Gn, 0);
    }

    // 4. word BiLSTM scan -> d_z fp32 + z bf16
    lstm_scan_w<<<128, 256, 2*8*1024*4 + 256*8*4>>>(pgpre, pwtf, pwtb, pz,
                                                    pzhi, pzlo, N1, Ln, DATT);

    // 5. word attention
    gemm_wb<<<dim3(NBATT, M1/128), 256, GEMM_SMEM2>>>(pzhi, pzlo, pwWth, pwWtl,
                                                      word_b, word_p, pscp,
                                                      M1, ZKP, ZKP, DATT, 1);
    sum_scores<<<(M1 + 255)/256, 256>>>(pscp, psc, M1, NBATT);
    softmax_pool_kernel<<<N1, 256>>>(psc, pz, psenvec, Ln, DATT);

    // 6. sentence input
    build_sx_kernel<<<(N1*ZKP + 255)/256, 256>>>(seg, spe);
    fill_z2pos<<<(N1*(ZKP-2*Hn) + 255)/256, 256>>>(seg, spe);
    {
        dim3 g(Gn/128, N1/128);
        gemm_wb<<<g, 256, GEMM_SMEM2>>>(psxhi, psxlo, psihfh, psihfl, sb_f, (const float*)0,
                                        pgpre2, N1, Gn, ZKP, Gn, 0);
        gemm_wb<<<g, 256, GEMM_SMEM2>>>(psxhi, psxlo, psihbh, psihbl, sb_b, (const float*)0,
                                        pgpre2 + (size_t)N1*Gn, N1, Gn, ZKP, Gn, 0);
    }

    // 7. sentence BiLSTM scan -> d_z2 fp32 + z2 bf16, keeps hT
    lstm_scan_s<<<2*Bn, 256, 2*8*1024*4 + 256*4>>>(pgpre2, pstf, pstb, pz2,
                                                   pz2hi, pz2lo, phT, Bn, Sn, DATT);

    // 8. sentence attention
    gemm_wb<<<dim3(NBATT, N1/128), 256, GEMM_SMEM2>>>(pz2hi, pz2lo, psWth, psWtl,
                                                      sent_b, sent_p, pscp2,
                                                      N1, ZKP, ZKP, DATT, 1);
    sum_scores<<<(N1 + 255)/256, 256>>>(pscp2, psc2, N1, NBATT);
    softmax_pool_kernel<<<Bn, 256>>>(psc2, pz2, pdocvec, Sn, DATT);

    // 9. classifier head
    final_dense_kernel<<<Bn, 128>>>(dense_W, dense_b, outp);
}

// round 10
// speedup vs baseline: 1.7351x; 1.1147x over previous
#include <cuda_runtime.h>
#include <cuda_bf16.h>
#include <mma.h>
#include <cstdint>
#include <math.h>

using namespace nvcuda;

// ---------------- problem constants ----------------
#define Bn   32
#define Sn   16
#define Ln   64
#define En   300
#define Pn   100
#define Hn   256
#define Gn   1024
#define DATT 612
#define N1   (Bn*Sn)
#define M1   (N1*Ln)
#define DIN1 (En+Pn)
#define NBATT 5             // 640/128
#define XKP  416            // padded K for x (400)
#define ZKP  640            // padded K/N for 612

typedef unsigned long long u64;
typedef __nv_bfloat16 bf16;

// ---------------- scratch (device globals) ----------------------------------
__device__ float d_gpre[2*M1*Gn];
__device__ float d_z[M1*DATT];
__device__ float d_scp[M1*NBATT];
__device__ float d_scores[M1];
__device__ float d_senvec[N1*2*Hn];
__device__ float d_gpre2[2*N1*Gn];
__device__ float d_z2[N1*DATT];
__device__ float d_hT[2*Bn*Hn];
__device__ float d_scp2[N1*NBATT];
__device__ float d_scores2[N1];
__device__ float d_docvec[Bn*2*Hn];
__device__ float d_wtf[Hn*Gn];
__device__ float d_wtb[Hn*Gn];
__device__ float d_stf[Hn*Gn];
__device__ float d_stb[Hn*Gn];
__device__ bf16 g_xhi[M1*XKP];
__device__ bf16 g_xlo[M1*XKP];
__device__ bf16 g_zhi[(size_t)M1*ZKP];
__device__ bf16 g_zlo[(size_t)M1*ZKP];
__device__ bf16 g_sxhi[N1*ZKP];
__device__ bf16 g_sxlo[N1*ZKP];
__device__ bf16 g_z2hi[N1*ZKP];
__device__ bf16 g_z2lo[N1*ZKP];
__device__ bf16 g_wihf_hi[Gn*XKP];
__device__ bf16 g_wihf_lo[Gn*XKP];
__device__ bf16 g_wihb_hi[Gn*XKP];
__device__ bf16 g_wihb_lo[Gn*XKP];
__device__ bf16 g_sihf_hi[Gn*ZKP];
__device__ bf16 g_sihf_lo[Gn*ZKP];
__device__ bf16 g_sihb_hi[Gn*ZKP];
__device__ bf16 g_sihb_lo[Gn*ZKP];
__device__ bf16 g_wWt_hi[ZKP*ZKP];
__device__ bf16 g_wWt_lo[ZKP*ZKP];
__device__ bf16 g_sWt_hi[ZKP*ZKP];
__device__ bf16 g_sWt_lo[ZKP*ZKP];

__device__ __forceinline__ float sigmoidf(float x) { return 1.0f / (1.0f + expf(-x)); }

__device__ __forceinline__ void fma2(u64& d, u64 a, u64 b) {
    asm("fma.rn.f32x2 %0, %1, %2, %3;" : "=l"(d) : "l"(a), "l"(b), "l"(d));
}
__device__ __forceinline__ u64 pack2(float x, float y) {
    u64 r; asm("mov.b64 %0, {%1,%2};" : "=l"(r) : "f"(x), "f"(y)); return r;
}
__device__ __forceinline__ void unpack2(float& lo, float& hi, u64 v) {
    asm("mov.b64 {%0,%1}, %2;" : "=f"(lo), "=f"(hi) : "l"(v));
}
__device__ __forceinline__ void split_bf16(float v, bf16& h, bf16& l) {
    h = __float2bfloat16(v);
    l = __float2bfloat16(v - __bfloat162float(h));
}
__device__ __forceinline__ uint32_t smem_u32(const void* p) {
    return (uint32_t)__cvta_generic_to_shared(p);
}
__device__ __forceinline__ void cp16(uint32_t dst, const void* src) {
    asm volatile("cp.async.cg.shared.global [%0], [%1], 16;" :: "r"(dst), "l"(src));
}
#define CP_COMMIT() asm volatile("cp.async.commit_group;" ::: "memory")
#define CP_WAIT0()  asm volatile("cp.async.wait_group 0;" ::: "memory")

// ======================= WMMA split-bf16 GEMM, 128x128 tile ==================
// C[M,Nc] = A[M,KP] @ B[*,KP]^T, pre-split bf16 hi/lo, KP mult of 32,
// M mult 128, Nc mult 128. cp.async double buffer, K-step 32.
// Tiles padded to 40-elem (80B) rows -> conflict-free LDSM.
// attn==0: C[m*Nc+n] = acc + bias[n]
// attn!=0: C[m*gridDim.x + bx] = sum_{n<Nv} tanh(acc+bias[n])*proj[n]
// smem: 2 stages x 4 tiles x (128x40 bf16 = 10240B) = 81920B;
// epilogue reuses [0,65536) as 128x128 f32 out tile; red[256] at +81920.
#define TSE   5120            // tile stride, elems
#define SSE   20480           // stage stride, elems
#define GEMM_SMEM2 82944

__global__ __launch_bounds__(256, 2)
void gemm_wb(const bf16* __restrict__ Ahi, const bf16* __restrict__ Alo,
             const bf16* __restrict__ Bhi, const bf16* __restrict__ Blo,
             const float* __restrict__ bias, const float* __restrict__ proj,
             float* __restrict__ C, int M, int Nc, int KP, int Nv, int attn)
{
    extern __shared__ float dynsm[];
    bf16* sb    = (bf16*)dynsm;      // staged tiles
    float* outs = dynsm;             // reused after mainloop
    float* red  = dynsm + 20480;     // byte 81920

    const int tid = threadIdx.x;
    const int m0 = blockIdx.y * 128;
    const int n0 = blockIdx.x * 128;
    const int w  = tid >> 5;
    const int wm = w >> 1;           // 0..3  (32-row band)
    const int wn = w & 1;            // 0..1  (64-col band)

    wmma::fragment<wmma::accumulator, 16, 16, 16, float> acc[2][4];
#pragma unroll
    for (int i = 0; i < 2; i++)
#pragma unroll
        for (int j = 0; j < 4; j++)
            wmma::fill_fragment(acc[i][j], 0.0f);

    const int nk   = KP / 32;
    const int rowi = tid >> 1;               // 0..127
    const int kof  = (tid & 1) * 16;         // bf16 elems
    const uint32_t sbase = smem_u32(sb);
    const uint32_t boff  = (uint32_t)(rowi * 80 + kof * 2);   // bytes in tile

    const bf16* __restrict__ pah = Ahi + (size_t)(m0 + rowi) * KP + kof;
    const bf16* __restrict__ pal = Alo + (size_t)(m0 + rowi) * KP + kof;
    const bf16* __restrict__ pbh = Bhi + (size_t)(n0 + rowi) * KP + kof;
    const bf16* __restrict__ pbl = Blo + (size_t)(n0 + rowi) * KP + kof;

    // stage chunk 0 into buffer 0
    // (Ah @ +0, Al @ +10240, Bh @ +20480, Bl @ +30720 bytes; stage stride 40960B)
    {
        const uint32_t d0 = sbase + boff;
        cp16(d0 +     0, pah);     cp16(d0 +    16, pah + 8);
        cp16(d0 + 10240, pal);     cp16(d0 + 10240 + 16, pal + 8);
        cp16(d0 + 20480, pbh);     cp16(d0 + 20480 + 16, pbh + 8);
        cp16(d0 + 30720, pbl);     cp16(d0 + 30720 + 16, pbl + 8);
        CP_COMMIT();
        CP_WAIT0();
    }
    __syncthreads();

    for (int kc = 0; kc < nk; kc++) {
        const int cur = kc & 1;
        if (kc + 1 < nk) {
            const int go = (kc + 1) * 32;
            const uint32_t d1 = sbase + (uint32_t)((cur ^ 1) * 40960) + boff;
            cp16(d1 +     0, pah + go);     cp16(d1 +    16, pah + go + 8);
            cp16(d1 + 10240, pal + go);     cp16(d1 + 10240 + 16, pal + go + 8);
            cp16(d1 + 20480, pbh + go);     cp16(d1 + 20480 + 16, pbh + go + 8);
            cp16(d1 + 30720, pbl + go);     cp16(d1 + 30720 + 16, pbl + go + 8);
            CP_COMMIT();
        }
        const bf16* Ah = sb + cur * SSE;
        const bf16* Al = Ah + TSE;
        const bf16* Bh = Ah + 2 * TSE;
        const bf16* Bl = Ah + 3 * TSE;
#pragma unroll
        for (int kf = 0; kf < 2; kf++) {
            wmma::fragment<wmma::matrix_a, 16, 16, 16, bf16, wmma::row_major> ah[2], al[2];
            wmma::fragment<wmma::matrix_b, 16, 16, 16, bf16, wmma::col_major> bh[4], bl[4];
#pragma unroll
            for (int i = 0; i < 2; i++) {
                wmma::load_matrix_sync(ah[i], Ah + (wm*32 + i*16)*40 + kf*16, 40);
                wmma::load_matrix_sync(al[i], Al + (wm*32 + i*16)*40 + kf*16, 40);
            }
#pragma unroll
            for (int j = 0; j < 4; j++) {
                wmma::load_matrix_sync(bh[j], Bh + (wn*64 + j*16)*40 + kf*16, 40);
                wmma::load_matrix_sync(bl[j], Bl + (wn*64 + j*16)*40 + kf*16, 40);
            }
#pragma unroll
            for (int i = 0; i < 2; i++) {
#pragma unroll
                for (int j = 0; j < 4; j++) {
                    wmma::mma_sync(acc[i][j], ah[i], bh[j], acc[i][j]);
                    wmma::mma_sync(acc[i][j], ah[i], bl[j], acc[i][j]);
                    wmma::mma_sync(acc[i][j], al[i], bh[j], acc[i][j]);
                }
            }
        }
        if (kc + 1 < nk) CP_WAIT0();
        __syncthreads();
    }

    // epilogue: reuse smem as fp32 out tile [128][128]
#pragma unroll
    for (int i = 0; i < 2; i++)
#pragma unroll
        for (int j = 0; j < 4; j++)
            wmma::store_matrix_sync(outs + (size_t)(wm*32 + i*16)*128 + wn*64 + j*16,
                                    acc[i][j], 128, wmma::mem_row_major);
    __syncthreads();

    if (attn == 0) {
        for (int i = tid; i < 128*128; i += 256) {
            int row = i >> 7;
            int col = i & 127;
            C[(size_t)(m0 + row) * Nc + n0 + col] = outs[i] + bias[n0 + col];
        }
    } else {
        const int row = tid >> 1;
        const int hf  = (tid & 1) * 64;
        float part = 0.f;
#pragma unroll
        for (int c = 0; c < 64; c++) {
            int n = n0 + hf + c;
            if (n < Nv) part += tanhf(outs[row*128 + hf + c] + bias[n]) * proj[n];
        }
        red[tid] = part;
        __syncthreads();
        if (tid < 128) {
            C[(size_t)(m0 + tid) * gridDim.x + blockIdx.x] = red[2*tid] + red[2*tid + 1];
        }
    }
}

// ---------------- gather: x bf16 hi/lo + z pos cols bf16 ----------------------
__global__ void gather_x_kernel(const int* __restrict__ tok,
                                const int* __restrict__ wpos,
                                const float* __restrict__ emb,
                                const float* __restrict__ wpe)
{
    int idx = blockIdx.x * blockDim.x + threadIdx.x;
    if (idx >= M1 * DIN1) return;
    int d = idx % DIN1;
    int m = idx / DIN1;
    float v;
    if (d < En) {
        v = emb[(size_t)tok[m] * En + d];
    } else {
        v = wpe[(size_t)wpos[m] * Pn + (d - En)];
        bf16 h, l;
        split_bf16(v, h, l);
        size_t zi = (size_t)m * ZKP + 2*Hn + (d - En);
        g_zhi[zi] = h;
        g_zlo[zi] = l;
    }
    bf16 h, l;
    split_bf16(v, h, l);
    g_xhi[(size_t)m * XKP + d] = h;
    g_xlo[(size_t)m * XKP + d] = l;
}

__global__ void pad_x_kernel()
{
    int idx = blockIdx.x * blockDim.x + threadIdx.x;
    if (idx >= M1 * (XKP - DIN1)) return;
    int m = idx / (XKP - DIN1);
    int k = DIN1 + idx % (XKP - DIN1);
    g_xhi[(size_t)m * XKP + k] = __float2bfloat16(0.f);
    g_xlo[(size_t)m * XKP + k] = __float2bfloat16(0.f);
}

__global__ void pad_z_kernel()
{
    int idx = blockIdx.x * blockDim.x + threadIdx.x;
    if (idx >= M1 * (ZKP - DATT)) return;
    int m = idx / (ZKP - DATT);
    int k = DATT + idx % (ZKP - DATT);
    g_zhi[(size_t)m * ZKP + k] = __float2bfloat16(0.f);
    g_zlo[(size_t)m * ZKP + k] = __float2bfloat16(0.f);
}

// ---------------- weight conversions -------------------------------------------
__global__ void conv_pad(const float* __restrict__ W, bf16* __restrict__ hi,
                         bf16* __restrict__ lo, int rows, int kc, int kp)
{
    int idx = blockIdx.x * blockDim.x + threadIdx.x;
    if (idx >= rows * kp) return;
    int r = idx / kp;
    int k = idx % kp;
    float v = (k < kc) ? W[(size_t)r * kc + k] : 0.f;
    bf16 h, l;
    split_bf16(v, h, l);
    hi[idx] = h;
    lo[idx] = l;
}

__global__ void conv_wt(const float* __restrict__ W, bf16* __restrict__ hi,
                        bf16* __restrict__ lo, int d, int np, int kp)
{
    int idx = blockIdx.x * blockDim.x + threadIdx.x;
    if (idx >= np * kp) return;
    int e = idx / kp;
    int k = idx % kp;
    float v = (e < d && k < d) ? W[(size_t)k * d + e] : 0.f;
    bf16 h, l;
    split_bf16(v, h, l);
    hi[idx] = h;
    lo[idx] = l;
}

// ---------------- transpose (Whh for scans) -------------------------------------
__global__ void transpose_k(const float* __restrict__ W, float* __restrict__ Wt,
                            int Gr, int Kc)
{
    int idx = blockIdx.x * blockDim.x + threadIdx.x;
    if (idx >= Gr * Kc) return;
    int g = idx / Kc;
    int k = idx % Kc;
    Wt[(size_t)k * Gr + g] = W[idx];
}

// ---------------- word BiLSTM scan (8 rows/block) ------------------------------
__global__ __launch_bounds__(256, 1)
void lstm_scan_w(const float* __restrict__ gpre,
                 const float* __restrict__ Wt_f,
                 const float* __restrict__ Wt_b,
                 float* __restrict__ out,
                 bf16* __restrict__ zhi, bf16* __restrict__ zlo,
                 int N, int T, int ostride)
{
    extern __shared__ float dynsm[];
    float* ws = dynsm;
    float* hs = dynsm + 2*8*1024;
    const int tid = threadIdx.x;
    const int nb  = N / 8;
    const int dir = blockIdx.x / nb;
    const int n0  = (blockIdx.x % nb) * 8;
    const float* __restrict__ Wt = dir ? Wt_b : Wt_f;

    float c[8];
#pragma unroll
    for (int r = 0; r < 8; r++) c[r] = 0.f;
    for (int i = tid; i < 256*8; i += 256) hs[i] = 0.f;

#pragma unroll
    for (int i = 0; i < 8; i++) {
        *(float4*)&ws[(tid + 256*i)*4] = *(const float4*)&Wt[(tid + 256*i)*4];
    }
    __syncthreads();

    const int NT = 32;
    for (int step = 0; step < T; step++) {
        const int tt = dir ? (T - 1 - step) : step;
        u64 acc2[4][4];
#pragma unroll
        for (int rp = 0; rp < 4; rp++) {
            size_t b0 = ((size_t)(dir*N + n0 + rp*2    ) * T + tt) * Gn;
            size_t b1 = ((size_t)(dir*N + n0 + rp*2 + 1) * T + tt) * Gn;
#pragma unroll
            for (int g = 0; g < 4; g++) {
                acc2[rp][g] = pack2(gpre[b0 + g*256 + tid], gpre[b1 + g*256 + tid]);
            }
        }
        for (int kt = 0; kt < NT; kt++) {
            const int cur = kt & 1;
            const bool last = (step == T-1) && (kt == NT-1);
            float4 pf[8];
            if (!last) {
                const float* src = &Wt[(size_t)((kt + 1) & 31) * 8192];
#pragma unroll
                for (int i = 0; i < 8; i++) {
                    pf[i] = *(const float4*)&src[(tid + 256*i)*4];
                }
            }
#pragma unroll
            for (int kk = 0; kk < 8; kk++) {
                const int k = kt*8 + kk;
                const float* wrow = &ws[(cur*8 + kk)*1024];
                float w0 = wrow[tid];
                float w1 = wrow[256+tid];
                float w2 = wrow[512+tid];
                float w3 = wrow[768+tid];
                u64 wd0 = pack2(w0,w0);
                u64 wd1 = pack2(w1,w1);
                u64 wd2 = pack2(w2,w2);
                u64 wd3 = pack2(w3,w3);
#pragma unroll
                for (int rp = 0; rp < 4; rp++) {
                    u64 h2 = *(const u64*)&hs[k*8 + rp*2];
                    fma2(acc2[rp][0], h2, wd0);
                    fma2(acc2[rp][1], h2, wd1);
                    fma2(acc2[rp][2], h2, wd2);
                    fma2(acc2[rp][3], h2, wd3);
                }
            }
            if (!last) {
                float* dst = &ws[(cur ^ 1) * 8192];
#pragma unroll
                for (int i = 0; i < 8; i++) {
                    *(float4*)&dst[(tid + 256*i)*4] = pf[i];
                }
            }
            __syncthreads();
        }
#pragma unroll
        for (int rp = 0; rp < 4; rp++) {
            float p0[2];
            float p1[2];
            float p2[2];
            float p3[2];
            unpack2(p0[0], p0[1], acc2[rp][0]);
            unpack2(p1[0], p1[1], acc2[rp][1]);
            unpack2(p2[0], p2[1], acc2[rp][2]);
            unpack2(p3[0], p3[1], acc2[rp][3]);
#pragma unroll
            for (int hh = 0; hh < 2; hh++) {
                int r = rp*2 + hh;
                float iv = sigmoidf(p0[hh]);
                float fv = sigmoidf(p1[hh]);
                float gv = tanhf(p2[hh]);
                float ov = sigmoidf(p3[hh]);
                c[r] = fv * c[r] + iv * gv;
                float hv = ov * tanhf(c[r]);
                hs[tid*8 + r] = hv;
                size_t mrow = (size_t)(n0 + r) * T + tt;
                out[mrow * ostride + dir*256 + tid] = hv;
                bf16 bh, bl;
                split_bf16(hv, bh, bl);
                zhi[mrow * ZKP + dir*256 + tid] = bh;
                zlo[mrow * ZKP + dir*256 + tid] = bl;
            }
        }
        __syncthreads();
    }
}

// ---------------- sentence BiLSTM scan (1 row/block, keeps hT) ------------------
__global__ __launch_bounds__(256, 1)
void lstm_scan_s(const float* __restrict__ gpre,
                 const float* __restrict__ Wt_f,
                 const float* __restrict__ Wt_b,
                 float* __restrict__ out,
                 bf16* __restrict__ zhi, bf16* __restrict__ zlo,
                 float* __restrict__ hT,
                 int N, int T, int ostride)
{
    extern __shared__ float dynsm[];
    float* ws = dynsm;
    float* hs = dynsm + 2*8*1024;
    const int tid = threadIdx.x;
    const int dir = blockIdx.x / N;
    const int n0  = blockIdx.x % N;
    const float* __restrict__ Wt = dir ? Wt_b : Wt_f;

    float c0 = 0.f;
    hs[tid] = 0.f;

#pragma unroll
    for (int i = 0; i < 8; i++) {
        *(float4*)&ws[(tid + 256*i)*4] = *(const float4*)&Wt[(tid + 256*i)*4];
    }
    __syncthreads();

    const int NT = 32;
    for (int step = 0; step < T; step++) {
        const int tt = dir ? (T - 1 - step) : step;
        float acc[4];
        size_t b0 = ((size_t)(dir*N + n0) * T + tt) * Gn;
#pragma unroll
        for (int g = 0; g < 4; g++) {
            acc[g] = gpre[b0 + g*256 + tid];
        }
        for (int kt = 0; kt < NT; kt++) {
            const int cur = kt & 1;
            const bool last = (step == T-1) && (kt == NT-1);
            float4 pf[8];
            if (!last) {
                const float* src = &Wt[(size_t)((kt + 1) & 31) * 8192];
#pragma unroll
                for (int i = 0; i < 8; i++) {
                    pf[i] = *(const float4*)&src[(tid + 256*i)*4];
                }
            }
#pragma unroll
            for (int kk = 0; kk < 8; kk++) {
                const int k = kt*8 + kk;
                const float* wrow = &ws[(cur*8 + kk)*1024];
                float hv = hs[k];
                acc[0] += hv * wrow[tid];
                acc[1] += hv * wrow[256+tid];
                acc[2] += hv * wrow[512+tid];
                acc[3] += hv * wrow[768+tid];
            }
            if (!last) {
                float* dst = &ws[(cur ^ 1) * 8192];
#pragma unroll
                for (int i = 0; i < 8; i++) {
                    *(float4*)&dst[(tid + 256*i)*4] = pf[i];
                }
            }
            __syncthreads();
        }
        float iv = sigmoidf(acc[0]);
        float fv = sigmoidf(acc[1]);
        float gv = tanhf(acc[2]);
        float ov = sigmoidf(acc[3]);
        c0 = fv * c0 + iv * gv;
        float hv = ov * tanhf(c0);
        hs[tid] = hv;
        size_t mrow = (size_t)n0 * T + tt;
        out[mrow * ostride + dir*256 + tid] = hv;
        bf16 bh, bl;
        split_bf16(hv, bh, bl);
        zhi[mrow * ZKP + dir*256 + tid] = bh;
        zlo[mrow * ZKP + dir*256 + tid] = bl;
        if (step == T - 1) {
            hT[((size_t)dir * N + n0) * 256 + tid] = hv;
        }
        __syncthreads();
    }
}

// ---------------- attention glue -----------------------------------------------
__global__ void sum_scores(const float* __restrict__ scp, float* __restrict__ sc,
                           int M, int NB)
{
    int m = blockIdx.x * blockDim.x + threadIdx.x;
    if (m >= M) return;
    float s = 0.f;
    for (int j = 0; j < NB; j++) s += scp[(size_t)m * NB + j];
    sc[m] = s;
}

__global__ void softmax_pool_kernel(const float* __restrict__ sc,
                                    const float* __restrict__ hsrc,
                                    float* __restrict__ outv,
                                    int T, int stride)
{
    __shared__ float a[64];
    __shared__ float inv_s;
    int n = blockIdx.x;
    int tid = threadIdx.x;
    if (tid == 0) {
        float mx = -1e30f;
        for (int t = 0; t < T; t++) mx = fmaxf(mx, sc[n * T + t]);
        float sum = 0.f;
        for (int t = 0; t < T; t++) {
            float e = expf(sc[n * T + t] - mx);
            a[t] = e;
            sum += e;
        }
        inv_s = 1.f / sum;
    }
    __syncthreads();
    float inv = inv_s;
    for (int col = tid; col < 2*Hn; col += blockDim.x) {
        float acc = 0.f;
        for (int t = 0; t < T; t++) {
            acc += a[t] * hsrc[((size_t)n * T + t) * stride + col];
        }
        outv[(size_t)n * (2*Hn) + col] = acc * inv;
    }
}

__global__ void build_sx_kernel(const int* __restrict__ seg,
                                const float* __restrict__ spe)
{
    int idx = blockIdx.x * blockDim.x + threadIdx.x;
    if (idx >= N1 * ZKP) return;
    int d = idx % ZKP;
    int m = idx / ZKP;
    float v;
    if (d < 2*Hn)      v = d_senvec[(size_t)m * (2*Hn) + d];
    else if (d < DATT) v = spe[(size_t)seg[m] * Pn + (d - 2*Hn)];
    else               v = 0.f;
    bf16 h, l;
    split_bf16(v, h, l);
    g_sxhi[idx] = h;
    g_sxlo[idx] = l;
}

__global__ void fill_z2pos(const int* __restrict__ seg, const float* __restrict__ spe)
{
    int idx = blockIdx.x * blockDim.x + threadIdx.x;
    if (idx >= N1 * (ZKP - 2*Hn)) return;
    int m = idx / (ZKP - 2*Hn);
    int d = idx % (ZKP - 2*Hn);
    float v = (d < Pn) ? spe[(size_t)seg[m] * Pn + d] : 0.f;
    bf16 h, l;
    split_bf16(v, h, l);
    g_z2hi[(size_t)m * ZKP + 2*Hn + d] = h;
    g_z2lo[(size_t)m * ZKP + 2*Hn + d] = l;
}

// ---------------- classifier head ------------------------------------------------
__global__ void final_dense_kernel(const float* __restrict__ dW,
                                   const float* __restrict__ db,
                                   float* __restrict__ outp)
{
    __shared__ float r0[128];
    __shared__ float r1[128];
    __shared__ float r2[128];
    int b = blockIdx.x;
    int tid = threadIdx.x;
    float a0 = 0.f, a1 = 0.f, a2 = 0.f;
    for (int k = tid; k < 4*Hn; k += 128) {
        float f;
        if (k < 2*Hn)      f = d_docvec[b * 2*Hn + k];
        else if (k < 3*Hn) f = d_hT[(0 * Bn + b) * Hn + (k - 2*Hn)];
        else               f = d_hT[(1 * Bn + b) * Hn + (k - 3*Hn)];
        a0 += f * dW[0*4*Hn + k];
        a1 += f * dW[1*4*Hn + k];
        a2 += f * dW[2*4*Hn + k];
    }
    r0[tid] = a0;
    r1[tid] = a1;
    r2[tid] = a2;
    __syncthreads();
    for (int s = 64; s > 0; s >>= 1) {
        if (tid < s) {
            r0[tid] += r0[tid+s];
            r1[tid] += r1[tid+s];
            r2[tid] += r2[tid+s];
        }
        __syncthreads();
    }
    if (tid == 0) {
        outp[b*3+0] = r0[0] + db[0];
        outp[b*3+1] = r1[0] + db[1];
        outp[b*3+2] = r2[0] + db[2];
    }
}

// ---------------- host driver ------------------------------------------------------
extern "C" void kernel_launch(void* const* d_in, const int* in_sizes, int n_in,
                              void* d_out, int out_size)
{
    const int*   tok     = (const int*)d_in[0];
    const int*   wpos    = (const int*)d_in[1];
    const int*   seg     = (const int*)d_in[2];
    const float* emb     = (const float*)d_in[3];
    const float* wpe     = (const float*)d_in[4];
    const float* spe     = (const float*)d_in[5];
    const float* wWih_f  = (const float*)d_in[6];
    const float* wWhh_f  = (const float*)d_in[7];
    const float* wb_f    = (const float*)d_in[8];
    const float* wWih_b  = (const float*)d_in[9];
    const float* wWhh_b  = (const float*)d_in[10];
    const float* wb_b    = (const float*)d_in[11];
    const float* sWih_f  = (const float*)d_in[12];
    const float* sWhh_f  = (const float*)d_in[13];
    const float* sb_f    = (const float*)d_in[14];
    const float* sWih_b  = (const float*)d_in[15];
    const float* sWhh_b  = (const float*)d_in[16];
    const float* sb_b    = (const float*)d_in[17];
    const float* word_W  = (const float*)d_in[18];
    const float* word_b  = (const float*)d_in[19];
    const float* word_p  = (const float*)d_in[20];
    const float* sent_W  = (const float*)d_in[21];
    const float* sent_b  = (const float*)d_in[22];
    const float* sent_p  = (const float*)d_in[23];
    const float* dense_W = (const float*)d_in[24];
    const float* dense_b = (const float*)d_in[25];
    float* outp = (float*)d_out;

    float *pgpre, *pz, *pscp, *psc, *psenvec, *pgpre2, *pz2,
          *phT, *pscp2, *psc2, *pdocvec, *pwtf, *pwtb, *pstf, *pstb;
    bf16 *pxhi, *pxlo, *pzhi, *pzlo, *psxhi, *psxlo, *pz2hi, *pz2lo,
         *pwihfh, *pwihfl, *pwihbh, *pwihbl, *psihfh, *psihfl, *psihbh, *psihbl,
         *pwWth, *pwWtl, *psWth, *psWtl;
    cudaGetSymbolAddress((void**)&pgpre,   d_gpre);
    cudaGetSymbolAddress((void**)&pz,      d_z);
    cudaGetSymbolAddress((void**)&pscp,    d_scp);
    cudaGetSymbolAddress((void**)&psc,     d_scores);
    cudaGetSymbolAddress((void**)&psenvec, d_senvec);
    cudaGetSymbolAddress((void**)&pgpre2,  d_gpre2);
    cudaGetSymbolAddress((void**)&pz2,     d_z2);
    cudaGetSymbolAddress((void**)&phT,     d_hT);
    cudaGetSymbolAddress((void**)&pscp2,   d_scp2);
    cudaGetSymbolAddress((void**)&psc2,    d_scores2);
    cudaGetSymbolAddress((void**)&pdocvec, d_docvec);
    cudaGetSymbolAddress((void**)&pwtf,    d_wtf);
    cudaGetSymbolAddress((void**)&pwtb,    d_wtb);
    cudaGetSymbolAddress((void**)&pstf,    d_stf);
    cudaGetSymbolAddress((void**)&pstb,    d_stb);
    cudaGetSymbolAddress((void**)&pxhi,    g_xhi);
    cudaGetSymbolAddress((void**)&pxlo,    g_xlo);
    cudaGetSymbolAddress((void**)&pzhi,    g_zhi);
    cudaGetSymbolAddress((void**)&pzlo,    g_zlo);
    cudaGetSymbolAddress((void**)&psxhi,   g_sxhi);
    cudaGetSymbolAddress((void**)&psxlo,   g_sxlo);
    cudaGetSymbolAddress((void**)&pz2hi,   g_z2hi);
    cudaGetSymbolAddress((void**)&pz2lo,   g_z2lo);
    cudaGetSymbolAddress((void**)&pwihfh,  g_wihf_hi);
    cudaGetSymbolAddress((void**)&pwihfl,  g_wihf_lo);
    cudaGetSymbolAddress((void**)&pwihbh,  g_wihb_hi);
    cudaGetSymbolAddress((void**)&pwihbl,  g_wihb_lo);
    cudaGetSymbolAddress((void**)&psihfh,  g_sihf_hi);
    cudaGetSymbolAddress((void**)&psihfl,  g_sihf_lo);
    cudaGetSymbolAddress((void**)&psihbh,  g_sihb_hi);
    cudaGetSymbolAddress((void**)&psihbl,  g_sihb_lo);
    cudaGetSymbolAddress((void**)&pwWth,   g_wWt_hi);
    cudaGetSymbolAddress((void**)&pwWtl,   g_wWt_lo);
    cudaGetSymbolAddress((void**)&psWth,   g_sWt_hi);
    cudaGetSymbolAddress((void**)&psWtl,   g_sWt_lo);

    cudaFuncSetAttribute(lstm_scan_w, cudaFuncAttributeMaxDynamicSharedMemorySize,
                         2*8*1024*4 + 256*8*4);
    cudaFuncSetAttribute(lstm_scan_s, cudaFuncAttributeMaxDynamicSharedMemorySize,
                         2*8*1024*4 + 256*4);
    cudaFuncSetAttribute(gemm_wb, cudaFuncAttributeMaxDynamicSharedMemorySize,
                         GEMM_SMEM2);

    // 1. gather + padding
    gather_x_kernel<<<(M1*DIN1 + 255)/256, 256>>>(tok, wpos, emb, wpe);
    pad_x_kernel<<<(M1*(XKP-DIN1) + 255)/256, 256>>>();
    pad_z_kernel<<<(M1*(ZKP-DATT) + 255)/256, 256>>>();

    // 2. weight conversions + Whh transposes
    conv_pad<<<(Gn*XKP + 255)/256, 256>>>(wWih_f, pwihfh, pwihfl, Gn, DIN1, XKP);
    conv_pad<<<(Gn*XKP + 255)/256, 256>>>(wWih_b, pwihbh, pwihbl, Gn, DIN1, XKP);
    conv_pad<<<(Gn*ZKP + 255)/256, 256>>>(sWih_f, psihfh, psihfl, Gn, DATT, ZKP);
    conv_pad<<<(Gn*ZKP + 255)/256, 256>>>(sWih_b, psihbh, psihbl, Gn, DATT, ZKP);
    conv_wt<<<(ZKP*ZKP + 255)/256, 256>>>(word_W, pwWth, pwWtl, DATT, ZKP, ZKP);
    conv_wt<<<(ZKP*ZKP + 255)/256, 256>>>(sent_W, psWth, psWtl, DATT, ZKP, ZKP);
    transpose_k<<<(Gn*Hn + 255)/256, 256>>>(wWhh_f, pwtf, Gn, Hn);
    transpose_k<<<(Gn*Hn + 255)/256, 256>>>(wWhh_b, pwtb, Gn, Hn);
    transpose_k<<<(Gn*Hn + 255)/256, 256>>>(sWhh_f, pstf, Gn, Hn);
    transpose_k<<<(Gn*Hn + 255)/256, 256>>>(sWhh_b, pstb, Gn, Hn);

    // 3. word input GEMMs
    {
        dim3 g(Gn/128, M1/128);
        gemm_wb<<<g, 256, GEMM_SMEM2>>>(pxhi, pxlo, pwihfh, pwihfl, wb_f, (const float*)0,
                                        pgpre, M1, Gn, XKP, Gn, 0);
        gemm_wb<<<g, 256, GEMM_SMEM2>>>(pxhi, pxlo, pwihbh, pwihbl, wb_b, (const float*)0,
                                        pgpre + (size_t)M1*Gn, M1, Gn, XKP, Gn, 0);
    }

    // 4. word BiLSTM scan -> d_z fp32 + z bf16
    lstm_scan_w<<<128, 256, 2*8*1024*4 + 256*8*4>>>(pgpre, pwtf, pwtb, pz,
                                                    pzhi, pzlo, N1, Ln, DATT);

    // 5. word attention
    gemm_wb<<<dim3(NBATT, M1/128), 256, GEMM_SMEM2>>>(pzhi, pzlo, pwWth, pwWtl,
                                                      word_b, word_p, pscp,
                                                      M1, ZKP, ZKP, DATT, 1);
    sum_scores<<<(M1 + 255)/256, 256>>>(pscp, psc, M1, NBATT);
    softmax_pool_kernel<<<N1, 256>>>(psc, pz, psenvec, Ln, DATT);

    // 6. sentence input
    build_sx_kernel<<<(N1*ZKP + 255)/256, 256>>>(seg, spe);
    fill_z2pos<<<(N1*(ZKP-2*Hn) + 255)/256, 256>>>(seg, spe);
    {
        dim3 g(Gn/128, N1/128);
        gemm_wb<<<g, 256, GEMM_SMEM2>>>(psxhi, psxlo, psihfh, psihfl, sb_f, (const float*)0,
                                        pgpre2, N1, Gn, ZKP, Gn, 0);
        gemm_wb<<<g, 256, GEMM_SMEM2>>>(psxhi, psxlo, psihbh, psihbl, sb_b, (const float*)0,
                                        pgpre2 + (size_t)N1*Gn, N1, Gn, ZKP, Gn, 0);
    }

    // 7. sentence BiLSTM scan -> d_z2 fp32 + z2 bf16, keeps hT
    lstm_scan_s<<<2*Bn, 256, 2*8*1024*4 + 256*4>>>(pgpre2, pstf, pstb, pz2,
                                                   pz2hi, pz2lo, phT, Bn, Sn, DATT);

    // 8. sentence attention
    gemm_wb<<<dim3(NBATT, N1/128), 256, GEMM_SMEM2>>>(pz2hi, pz2lo, psWth, psWtl,
                                                      sent_b, sent_p, pscp2,
                                                      N1, ZKP, ZKP, DATT, 1);
    sum_scores<<<(N1 + 255)/256, 256>>>(pscp2, psc2, N1, NBATT);
    softmax_pool_kernel<<<Bn, 256>>>(psc2, pz2, pdocvec, Sn, DATT);

    // 9. classifier head
    final_dense_kernel<<<Bn, 128>>>(dense_W, dense_b, outp);
}